// round 9
// baseline (speedup 1.0000x reference)
#include <cuda_runtime.h>
#include <cuda_bf16.h>
#include <cstdint>

// ---------------------------------------------------------------------------
// PlanStructuredNetwork via mma.sync bf16 (fp32 acc), bf16x3 split.
// R8 = R4 structure (the 2576us winner) +
//   (a) gather of next tile hidden under L3 via parity-cycled act buffers
//   (b) 4-way accumulator round-robin in the L1/L2 inner loop (more MMA ILP)
//   Leaf:  (B*1024, 32) -> 128 -> 128 -> 32
//   Join x10: (B*n, 96) -> 128 -> 128 -> 32,  n = 512..1
// ---------------------------------------------------------------------------

#define NB    2048
#define NLEAF 1024
#define FD    32
#define HD    128
#define OD    32

#define TILE_R  64
#define THREADS 512

__device__ float g_bufA[(size_t)NB * NLEAF * OD];        // 268 MB
__device__ float g_bufB[(size_t)NB * (NLEAF / 2) * OD];  // 134 MB

// --- smem byte offsets ---
// Two act buffers U,V; each 64 rows * 272 B, hi+lo planes. Roles cycle by
// tile parity: X in buf[p]; H1 -> buf[1-p]; H2 -> buf[p]; gather -> buf[1-p].
#define U_HI    0
#define U_LO    17408
#define V_HI    34816
#define V_LO    52224
#define W1T_HI  69632       // [128][104] bf16, stride 208
#define W1T_LO  96256
#define W2T_HI  122880      // [128][136] bf16, stride 272
#define W2T_LO  157696
#define W3T_HI  192512      // [32][136] bf16, stride 272
#define W3T_LO  201216
#define B1OFF   209920
#define B2OFF   210432
#define B3OFF   210944
#define SMEM_TOTAL 211072

#define AST     272         // activation row stride (136 bf16, conflict-free)
#define W1ST    208
#define W2ST    272
#define W3ST    272

// ---------------------------------------------------------------------------
__device__ __forceinline__ uint32_t smem_u32(const void* p) {
    uint32_t a;
    asm("{ .reg .u64 t; cvta.to.shared.u64 t, %1; cvt.u32.u64 %0, t; }"
        : "=r"(a) : "l"(p));
    return a;
}

#define LDSM_X4(r0, r1, r2, r3, addr)                                          \
    asm volatile("ldmatrix.sync.aligned.m8n8.x4.shared.b16 {%0,%1,%2,%3}, [%4];" \
                 : "=r"(r0), "=r"(r1), "=r"(r2), "=r"(r3) : "r"(addr))

#define LDSM_X2(r0, r1, addr)                                                  \
    asm volatile("ldmatrix.sync.aligned.m8n8.x2.shared.b16 {%0,%1}, [%2];"     \
                 : "=r"(r0), "=r"(r1) : "r"(addr))

#define MMA_BF16(c, a0, a1, a2, a3, b0, b1)                                    \
    asm volatile("mma.sync.aligned.m16n8k16.row.col.f32.bf16.bf16.f32 "        \
                 "{%0,%1,%2,%3}, {%4,%5,%6,%7}, {%8,%9}, {%0,%1,%2,%3};"       \
                 : "+f"((c)[0]), "+f"((c)[1]), "+f"((c)[2]), "+f"((c)[3])      \
                 : "r"(a0), "r"(a1), "r"(a2), "r"(a3), "r"(b0), "r"(b1))

__device__ __forceinline__ void split2(float v0, float v1, uint32_t& hi, uint32_t& lo) {
    __nv_bfloat16 h0 = __float2bfloat16(v0);
    __nv_bfloat16 h1 = __float2bfloat16(v1);
    float r0 = v0 - __bfloat162float(h0);
    float r1 = v1 - __bfloat162float(h1);
    __nv_bfloat16 l0 = __float2bfloat16(r0);
    __nv_bfloat16 l1 = __float2bfloat16(r1);
    hi = (uint32_t)__bfloat16_as_ushort(h0) | ((uint32_t)__bfloat16_as_ushort(h1) << 16);
    lo = (uint32_t)__bfloat16_as_ushort(l0) | ((uint32_t)__bfloat16_as_ushort(l1) << 16);
}

// ---------------------------------------------------------------------------
// L1/L2 GEMM: warp = 16 rows x 32 cols; per k-chunk load A hi/lo + all B
// frags, then 12 MMAs round-robin across the 4 accumulators (4-way ILP).
// C = Ahi*Bhi + Ahi*Blo + Alo*Bhi
// ---------------------------------------------------------------------------
template <int NK>
__device__ __forceinline__ void gemm3_rr(uint32_t sb,
                                         uint32_t aHiOff, uint32_t aLoOff, int astB,
                                         uint32_t bHiOff, uint32_t bLoOff, int bstB,
                                         int colBase, int lane, int wm,
                                         float c[4][4]) {
#pragma unroll
    for (int j = 0; j < 4; j++)
#pragma unroll
        for (int q = 0; q < 4; q++) c[j][q] = 0.f;

    const int aRow = wm * 16 + (lane & 15);
    const uint32_t aKb = (uint32_t)(lane >> 4) * 16;
    const uint32_t aHi = sb + aHiOff + (uint32_t)aRow * astB + aKb;
    const uint32_t aLo = sb + aLoOff + (uint32_t)aRow * astB + aKb;

    const int nLoc = (lane & 7) + ((lane >> 4) << 3);
    const uint32_t bKb = (uint32_t)((lane >> 3) & 1) * 16;
    const uint32_t bHi = sb + bHiOff + (uint32_t)(colBase + nLoc) * bstB + bKb;
    const uint32_t bLo = sb + bLoOff + (uint32_t)(colBase + nLoc) * bstB + bKb;

#pragma unroll
    for (int k = 0; k < NK; k++) {
        uint32_t ah0, ah1, ah2, ah3, al0, al1, al2, al3;
        LDSM_X4(ah0, ah1, ah2, ah3, aHi + k * 32);
        LDSM_X4(al0, al1, al2, al3, aLo + k * 32);
        uint32_t b0h0, b0h1, b0h2, b0h3, b0l0, b0l1, b0l2, b0l3;
        uint32_t b1h0, b1h1, b1h2, b1h3, b1l0, b1l1, b1l2, b1l3;
        LDSM_X4(b0h0, b0h1, b0h2, b0h3, bHi + k * 32);
        LDSM_X4(b0l0, b0l1, b0l2, b0l3, bLo + k * 32);
        LDSM_X4(b1h0, b1h1, b1h2, b1h3, bHi + 16 * bstB + k * 32);
        LDSM_X4(b1l0, b1l1, b1l2, b1l3, bLo + 16 * bstB + k * 32);
        // pass hi*hi (4-way round robin)
        MMA_BF16(c[0], ah0, ah1, ah2, ah3, b0h0, b0h1);
        MMA_BF16(c[1], ah0, ah1, ah2, ah3, b0h2, b0h3);
        MMA_BF16(c[2], ah0, ah1, ah2, ah3, b1h0, b1h1);
        MMA_BF16(c[3], ah0, ah1, ah2, ah3, b1h2, b1h3);
        // pass hi*lo
        MMA_BF16(c[0], ah0, ah1, ah2, ah3, b0l0, b0l1);
        MMA_BF16(c[1], ah0, ah1, ah2, ah3, b0l2, b0l3);
        MMA_BF16(c[2], ah0, ah1, ah2, ah3, b1l0, b1l1);
        MMA_BF16(c[3], ah0, ah1, ah2, ah3, b1l2, b1l3);
        // pass lo*hi
        MMA_BF16(c[0], al0, al1, al2, al3, b0h0, b0h1);
        MMA_BF16(c[1], al0, al1, al2, al3, b0h2, b0h3);
        MMA_BF16(c[2], al0, al1, al2, al3, b1h0, b1h1);
        MMA_BF16(c[3], al0, al1, al2, al3, b1h2, b1h3);
    }
}

// Epilogue (32 cols per warp): bias + ReLU + split -> act smem (stride 272)
__device__ __forceinline__ void epi128(char* smem, float c[4][4],
                                       uint32_t biasOff, uint32_t hiOff, uint32_t loOff,
                                       int lane, int wm, int colBase) {
    int r0 = wm * 16 + (lane >> 2);
#pragma unroll
    for (int t = 0; t < 4; t++) {
        int n0 = colBase + t * 8 + (lane & 3) * 2;
        float2 bb = *(const float2*)(smem + biasOff + n0 * 4);
        {
            float v0 = fmaxf(c[t][0] + bb.x, 0.f);
            float v1 = fmaxf(c[t][1] + bb.y, 0.f);
            uint32_t hi, lo;
            split2(v0, v1, hi, lo);
            uint32_t o = (uint32_t)r0 * AST + (uint32_t)n0 * 2;
            *(uint32_t*)(smem + hiOff + o) = hi;
            *(uint32_t*)(smem + loOff + o) = lo;
        }
        {
            float v0 = fmaxf(c[t][2] + bb.x, 0.f);
            float v1 = fmaxf(c[t][3] + bb.y, 0.f);
            uint32_t hi, lo;
            split2(v0, v1, hi, lo);
            uint32_t o = (uint32_t)(r0 + 8) * AST + (uint32_t)n0 * 2;
            *(uint32_t*)(smem + hiOff + o) = hi;
            *(uint32_t*)(smem + loOff + o) = lo;
        }
    }
}

// ---------------------------------------------------------------------------
// Gather: input tile -> (xHi,xLo) [row][k], stride 272. tg/nthr = thread subset.
// ---------------------------------------------------------------------------
template <int MODE>
__device__ __forceinline__ void do_gather(char* smem,
                                          const float* __restrict__ in,
                                          const float* __restrict__ prev,
                                          int row0, int logn, int off,
                                          uint32_t xHi, uint32_t xLo,
                                          int tg, int nthr) {
    if (MODE == 0) {
        const float2* src = (const float2*)(in + (size_t)row0 * FD);
        for (int i = tg; i < TILE_R * 16; i += nthr) {
            int r = i >> 4, cp = i & 15;
            float2 v = src[i];
            uint32_t hi, lo;
            split2(v.x, v.y, hi, lo);
            uint32_t o = (uint32_t)r * AST + (uint32_t)cp * 4;
            *(uint32_t*)(smem + xHi + o) = hi;
            *(uint32_t*)(smem + xLo + o) = lo;
        }
    } else {
        const int n = 1 << logn;
        for (int i = tg; i < TILE_R * 48; i += nthr) {
            int r = i / 48, cp = i - r * 48;
            int gr = row0 + r;
            int b = gr >> logn, ii = gr & (n - 1);
            float2 v;
            if (cp < 16)
                v = *(const float2*)(in + (((size_t)b * (NLEAF - 1) + off + ii) << 5) + cp * 2);
            else
                v = *(const float2*)(prev + (((size_t)(b << (logn + 1)) + 2 * ii) << 5) + (cp * 2 - 32));
            uint32_t hi, lo;
            split2(v.x, v.y, hi, lo);
            uint32_t o = (uint32_t)r * AST + (uint32_t)cp * 4;
            *(uint32_t*)(smem + xHi + o) = hi;
            *(uint32_t*)(smem + xLo + o) = lo;
        }
    }
}

// ---------------------------------------------------------------------------
// MODE: 0 = leaf (in -> bufA), 1 = join A->B, 2 = join B->A
// ---------------------------------------------------------------------------
template <int NK1, int MODE>
__global__ void __launch_bounds__(THREADS, 1)
level_kernel(const float* __restrict__ in,
             const float* __restrict__ W1, const float* __restrict__ b1,
             const float* __restrict__ W2, const float* __restrict__ b2,
             const float* __restrict__ W3, const float* __restrict__ b3,
             int logn, int off, int ntiles) {
    extern __shared__ char smem[];
    uint32_t sb = smem_u32(smem);
    const int tid = threadIdx.x;
    const int lane = tid & 31;
    const int wid = tid >> 5;
    const int wm = wid & 3;        // row group (16 rows)
    const int wn = wid >> 2;       // col group (32 cols L1/L2; 16 outs L3)
    const int K1 = NK1 * 16;

    // --- stage weights (transposed [N][K], hi/lo) + biases ---
    for (int i = tid; i < K1 * HD; i += THREADS) {
        int k = i / HD, n = i - k * HD;
        float v = W1[i];
        __nv_bfloat16 h = __float2bfloat16(v);
        __nv_bfloat16 l = __float2bfloat16(v - __bfloat162float(h));
        uint32_t o = (uint32_t)n * W1ST + (uint32_t)k * 2;
        *(__nv_bfloat16*)(smem + W1T_HI + o) = h;
        *(__nv_bfloat16*)(smem + W1T_LO + o) = l;
    }
    for (int i = tid; i < HD * HD; i += THREADS) {
        int k = i / HD, n = i - k * HD;
        float v = W2[i];
        __nv_bfloat16 h = __float2bfloat16(v);
        __nv_bfloat16 l = __float2bfloat16(v - __bfloat162float(h));
        uint32_t o = (uint32_t)n * W2ST + (uint32_t)k * 2;
        *(__nv_bfloat16*)(smem + W2T_HI + o) = h;
        *(__nv_bfloat16*)(smem + W2T_LO + o) = l;
    }
    for (int i = tid; i < HD * OD; i += THREADS) {
        int k = i / OD, n = i - k * OD;
        float v = W3[i];
        __nv_bfloat16 h = __float2bfloat16(v);
        __nv_bfloat16 l = __float2bfloat16(v - __bfloat162float(h));
        uint32_t o = (uint32_t)n * W3ST + (uint32_t)k * 2;
        *(__nv_bfloat16*)(smem + W3T_HI + o) = h;
        *(__nv_bfloat16*)(smem + W3T_LO + o) = l;
    }
    if (tid < HD) {
        ((float*)(smem + B1OFF))[tid] = b1[tid];
        ((float*)(smem + B2OFF))[tid] = b2[tid];
    }
    if (tid < OD) ((float*)(smem + B3OFF))[tid] = b3[tid];
    __syncthreads();

    const float* prev = (MODE == 1) ? g_bufA : g_bufB;
    float* dst = (MODE == 0) ? g_bufA : ((MODE == 1) ? g_bufB : g_bufA);
    const int G = gridDim.x;

    // prologue: gather first tile into U (parity 0)
    if (blockIdx.x < ntiles)
        do_gather<MODE>(smem, in, prev, blockIdx.x * TILE_R, logn, off,
                        U_HI, U_LO, tid, THREADS);
    __syncthreads();

    int p = 0;
    for (int t = blockIdx.x; t < ntiles; t += G, p ^= 1) {
        const int row0 = t * TILE_R;
        const uint32_t xHi = p ? V_HI : U_HI;   // X lives here; H2 returns here
        const uint32_t xLo = p ? V_LO : U_LO;
        const uint32_t hHi = p ? U_HI : V_HI;   // H1 here; next X gathered here
        const uint32_t hLo = p ? U_LO : V_LO;

        // ---- layer 1: X[64 x K1] @ W1T -> H1 ----
        {
            float c[4][4];
            gemm3_rr<NK1>(sb, xHi, xLo, AST, W1T_HI, W1T_LO, W1ST,
                          wn * 32, lane, wm, c);
            epi128(smem, c, B1OFF, hHi, hLo, lane, wm, wn * 32);
        }
        __syncthreads();

        // ---- layer 2: H1[64 x 128] @ W2T -> H2 (into X's buffer) ----
        {
            float c[4][4];
            gemm3_rr<8>(sb, hHi, hLo, AST, W2T_HI, W2T_LO, W2ST,
                        wn * 32, lane, wm, c);
            epi128(smem, c, B2OFF, xHi, xLo, lane, wm, wn * 32);
        }
        __syncthreads();

        // ---- layer 3 (warps 0-7) || gather next tile (warps 8-15) ----
        if (tid < 256) {
            float c[2][4];
#pragma unroll
            for (int j = 0; j < 2; j++)
#pragma unroll
                for (int q = 0; q < 4; q++) c[j][q] = 0.f;

            const int aRow = wm * 16 + (lane & 15);
            const uint32_t aKb = (uint32_t)(lane >> 4) * 16;
            const uint32_t aHi = sb + xHi + (uint32_t)aRow * AST + aKb;
            const uint32_t aLo = sb + xLo + (uint32_t)aRow * AST + aKb;

            const int l15 = lane & 15;
            const uint32_t bKb = (uint32_t)(l15 >> 3) * 16;
            const uint32_t bHi = sb + W3T_HI + (uint32_t)(wn * 16 + (l15 & 7)) * W3ST + bKb;
            const uint32_t bLo = sb + W3T_LO + (uint32_t)(wn * 16 + (l15 & 7)) * W3ST + bKb;

#pragma unroll
            for (int k = 0; k < 8; k++) {
                uint32_t ah0, ah1, ah2, ah3, al0, al1, al2, al3;
                LDSM_X4(ah0, ah1, ah2, ah3, aHi + k * 32);
                LDSM_X4(al0, al1, al2, al3, aLo + k * 32);
                uint32_t b0h0, b0h1, b0l0, b0l1, b1h0, b1h1, b1l0, b1l1;
                LDSM_X2(b0h0, b0h1, bHi + k * 32);
                LDSM_X2(b0l0, b0l1, bLo + k * 32);
                LDSM_X2(b1h0, b1h1, bHi + 8 * W3ST + k * 32);
                LDSM_X2(b1l0, b1l1, bLo + 8 * W3ST + k * 32);
                MMA_BF16(c[0], ah0, ah1, ah2, ah3, b0h0, b0h1);
                MMA_BF16(c[1], ah0, ah1, ah2, ah3, b1h0, b1h1);
                MMA_BF16(c[0], ah0, ah1, ah2, ah3, b0l0, b0l1);
                MMA_BF16(c[1], ah0, ah1, ah2, ah3, b1l0, b1l1);
                MMA_BF16(c[0], al0, al1, al2, al3, b0h0, b0h1);
                MMA_BF16(c[1], al0, al1, al2, al3, b1h0, b1h1);
            }

            int r0 = row0 + wm * 16 + (lane >> 2);
#pragma unroll
            for (int tt = 0; tt < 2; tt++) {
                int n0 = wn * 16 + tt * 8 + (lane & 3) * 2;
                float2 bb = *(const float2*)(smem + B3OFF + n0 * 4);
                float2 v0 = make_float2(c[tt][0] + bb.x, c[tt][1] + bb.y);
                float2 v1 = make_float2(c[tt][2] + bb.x, c[tt][3] + bb.y);
                *(float2*)(dst + (size_t)r0 * OD + n0) = v0;
                *(float2*)(dst + (size_t)(r0 + 8) * OD + n0) = v1;
            }
        } else {
            int tn = t + G;
            if (tn < ntiles)
                do_gather<MODE>(smem, in, prev, tn * TILE_R, logn, off,
                                hHi, hLo, tid - 256, 256);
        }
        __syncthreads();
    }
}

// ---------------------------------------------------------------------------
__global__ void extract_kernel(float* __restrict__ out) {
    int b = blockIdx.x * blockDim.x + threadIdx.x;
    if (b < NB) out[b] = g_bufA[(size_t)b * OD];
}

// ---------------------------------------------------------------------------
extern "C" void kernel_launch(void* const* d_in, const int* in_sizes, int n_in,
                              void* d_out, int out_size) {
    const float* leaf_feats = (const float*)d_in[0];
    const float* internal   = (const float*)d_in[1];
    const float* sW1 = (const float*)d_in[2];
    const float* sb1 = (const float*)d_in[3];
    const float* sW2 = (const float*)d_in[4];
    const float* sb2 = (const float*)d_in[5];
    const float* sW3 = (const float*)d_in[6];
    const float* sb3 = (const float*)d_in[7];
    const float* jW1 = (const float*)d_in[8];
    const float* jb1 = (const float*)d_in[9];
    const float* jW2 = (const float*)d_in[10];
    const float* jb2 = (const float*)d_in[11];
    const float* jW3 = (const float*)d_in[12];
    const float* jb3 = (const float*)d_in[13];
    float* out = (float*)d_out;

    cudaFuncSetAttribute(level_kernel<2, 0>, cudaFuncAttributeMaxDynamicSharedMemorySize, SMEM_TOTAL);
    cudaFuncSetAttribute(level_kernel<6, 1>, cudaFuncAttributeMaxDynamicSharedMemorySize, SMEM_TOTAL);
    cudaFuncSetAttribute(level_kernel<6, 2>, cudaFuncAttributeMaxDynamicSharedMemorySize, SMEM_TOTAL);

    // Leaf level: K1 = 32, dst = bufA
    {
        int ntiles = (NB * NLEAF) / TILE_R;     // 32768
        int grid = ntiles < 148 ? ntiles : 148;
        level_kernel<2, 0><<<grid, THREADS, SMEM_TOTAL>>>(
            leaf_feats, sW1, sb1, sW2, sb2, sW3, sb3, 0, 0, ntiles);
    }

    // Join levels n = 512..1; alternate A->B / B->A; final lands in bufA
    int off = 0;
    int mode = 1;
    for (int logn = 9; logn >= 0; --logn) {
        int n = 1 << logn;
        int ntiles = (NB * n) / TILE_R;
        int grid = ntiles < 148 ? ntiles : 148;
        if (mode == 1)
            level_kernel<6, 1><<<grid, THREADS, SMEM_TOTAL>>>(
                internal, jW1, jb1, jW2, jb2, jW3, jb3, logn, off, ntiles);
        else
            level_kernel<6, 2><<<grid, THREADS, SMEM_TOTAL>>>(
                internal, jW1, jb1, jW2, jb2, jW3, jb3, logn, off, ntiles);
        off += n;
        mode = (mode == 1) ? 2 : 1;
    }

    extract_kernel<<<(NB + 255) / 256, 256>>>(out);
}

// round 10
// speedup vs baseline: 1.0004x; 1.0004x over previous
#include <cuda_runtime.h>
#include <cuda_bf16.h>
#include <cstdint>

// ---------------------------------------------------------------------------
// PlanStructuredNetwork via mma.sync bf16 (fp32 acc), bf16x3 split.
// R10 = R4 (2576us winner) VERBATIM inner loops + exactly ONE change:
//   parity-cycled activation buffers so the next tile's gather runs on
//   warps 8-15 during L3 (which only uses warps 0-7 in R4 anyway).
//   Leaf:  (B*1024, 32) -> 128 -> 128 -> 32
//   Join x10: (B*n, 96) -> 128 -> 128 -> 32,  n = 512..1
// ---------------------------------------------------------------------------

#define NB    2048
#define NLEAF 1024
#define FD    32
#define HD    128
#define OD    32

#define TILE_R  64
#define THREADS 512

__device__ float g_bufA[(size_t)NB * NLEAF * OD];        // 268 MB
__device__ float g_bufB[(size_t)NB * (NLEAF / 2) * OD];  // 134 MB

// --- smem byte offsets ---
// Two act buffers U,V; each 64 rows * 272 B, hi+lo planes. Roles cycle by
// tile parity: X in buf[p]; H1 -> buf[1-p]; H2 -> buf[p] (X dead);
// L3 reads buf[p] while warps 8-15 gather next X -> buf[1-p] (H1 dead).
#define U_HI    0
#define U_LO    17408
#define V_HI    34816
#define V_LO    52224
#define W1T_HI  69632       // [128][104] bf16, stride 208
#define W1T_LO  96256
#define W2T_HI  122880      // [128][136] bf16, stride 272
#define W2T_LO  157696
#define W3T_HI  192512      // [32][136] bf16, stride 272
#define W3T_LO  201216
#define B1OFF   209920
#define B2OFF   210432
#define B3OFF   210944
#define SMEM_TOTAL 211072

#define AST     272         // activation row stride (136 bf16, conflict-free)
#define W1ST    208
#define W2ST    272
#define W3ST    272

// ---------------------------------------------------------------------------
__device__ __forceinline__ uint32_t smem_u32(const void* p) {
    uint32_t a;
    asm("{ .reg .u64 t; cvta.to.shared.u64 t, %1; cvt.u32.u64 %0, t; }"
        : "=r"(a) : "l"(p));
    return a;
}

#define LDSM_X4(r0, r1, r2, r3, addr)                                          \
    asm volatile("ldmatrix.sync.aligned.m8n8.x4.shared.b16 {%0,%1,%2,%3}, [%4];" \
                 : "=r"(r0), "=r"(r1), "=r"(r2), "=r"(r3) : "r"(addr))

#define LDSM_X2(r0, r1, addr)                                                  \
    asm volatile("ldmatrix.sync.aligned.m8n8.x2.shared.b16 {%0,%1}, [%2];"     \
                 : "=r"(r0), "=r"(r1) : "r"(addr))

#define MMA_BF16(c, a0, a1, a2, a3, b0, b1)                                    \
    asm volatile("mma.sync.aligned.m16n8k16.row.col.f32.bf16.bf16.f32 "        \
                 "{%0,%1,%2,%3}, {%4,%5,%6,%7}, {%8,%9}, {%0,%1,%2,%3};"       \
                 : "+f"((c)[0]), "+f"((c)[1]), "+f"((c)[2]), "+f"((c)[3])      \
                 : "r"(a0), "r"(a1), "r"(a2), "r"(a3), "r"(b0), "r"(b1))

__device__ __forceinline__ void split2(float v0, float v1, uint32_t& hi, uint32_t& lo) {
    __nv_bfloat16 h0 = __float2bfloat16(v0);
    __nv_bfloat16 h1 = __float2bfloat16(v1);
    float r0 = v0 - __bfloat162float(h0);
    float r1 = v1 - __bfloat162float(h1);
    __nv_bfloat16 l0 = __float2bfloat16(r0);
    __nv_bfloat16 l1 = __float2bfloat16(r1);
    hi = (uint32_t)__bfloat16_as_ushort(h0) | ((uint32_t)__bfloat16_as_ushort(h1) << 16);
    lo = (uint32_t)__bfloat16_as_ushort(l0) | ((uint32_t)__bfloat16_as_ushort(l1) << 16);
}

// ---------------------------------------------------------------------------
// L1/L2 GEMM — EXACT R4 loop: warp = 16 rows x 32 cols, B loaded just-in-time
// per n-pair, 6 MMAs per pair. C = Ahi*Bhi + Ahi*Blo + Alo*Bhi
// ---------------------------------------------------------------------------
template <int NT2, int NK>
__device__ __forceinline__ void gemm3_x4(uint32_t sb,
                                         uint32_t aHiOff, uint32_t aLoOff, int astB,
                                         uint32_t bHiOff, uint32_t bLoOff, int bstB,
                                         int colBase, int lane, int wm,
                                         float c[][4]) {
#pragma unroll
    for (int j = 0; j < 2 * NT2; j++)
#pragma unroll
        for (int q = 0; q < 4; q++) c[j][q] = 0.f;

    const int aRow = wm * 16 + (lane & 15);
    const uint32_t aKb = (uint32_t)(lane >> 4) * 16;
    const uint32_t aHi = sb + aHiOff + (uint32_t)aRow * astB + aKb;
    const uint32_t aLo = sb + aLoOff + (uint32_t)aRow * astB + aKb;

    const int nLoc = (lane & 7) + ((lane >> 4) << 3);
    const uint32_t bKb = (uint32_t)((lane >> 3) & 1) * 16;
    const uint32_t bHi = sb + bHiOff + (uint32_t)(colBase + nLoc) * bstB + bKb;
    const uint32_t bLo = sb + bLoOff + (uint32_t)(colBase + nLoc) * bstB + bKb;

#pragma unroll
    for (int k = 0; k < NK; k++) {
        uint32_t ah0, ah1, ah2, ah3, al0, al1, al2, al3;
        LDSM_X4(ah0, ah1, ah2, ah3, aHi + k * 32);
        LDSM_X4(al0, al1, al2, al3, aLo + k * 32);
#pragma unroll
        for (int j = 0; j < NT2; j++) {
            uint32_t bh0, bh1, bh2, bh3, bl0, bl1, bl2, bl3;
            LDSM_X4(bh0, bh1, bh2, bh3, bHi + j * 16 * bstB + k * 32);
            LDSM_X4(bl0, bl1, bl2, bl3, bLo + j * 16 * bstB + k * 32);
            MMA_BF16(c[2 * j],     ah0, ah1, ah2, ah3, bh0, bh1);
            MMA_BF16(c[2 * j + 1], ah0, ah1, ah2, ah3, bh2, bh3);
            MMA_BF16(c[2 * j],     ah0, ah1, ah2, ah3, bl0, bl1);
            MMA_BF16(c[2 * j + 1], ah0, ah1, ah2, ah3, bl2, bl3);
            MMA_BF16(c[2 * j],     al0, al1, al2, al3, bh0, bh1);
            MMA_BF16(c[2 * j + 1], al0, al1, al2, al3, bh2, bh3);
        }
    }
}

// L3 GEMM — EXACT R4 loop: warp = 16 rows x 16 cols via x2 B loads.
template <int NT, int NK>
__device__ __forceinline__ void gemm3_x2(uint32_t sb,
                                         uint32_t aHiOff, uint32_t aLoOff, int astB,
                                         uint32_t bHiOff, uint32_t bLoOff, int bstB,
                                         int colBase, int lane, int wm,
                                         float c[][4]) {
#pragma unroll
    for (int j = 0; j < NT; j++)
#pragma unroll
        for (int q = 0; q < 4; q++) c[j][q] = 0.f;

    const int aRow = wm * 16 + (lane & 15);
    const uint32_t aKb = (uint32_t)(lane >> 4) * 16;
    const uint32_t aHi = sb + aHiOff + (uint32_t)aRow * astB + aKb;
    const uint32_t aLo = sb + aLoOff + (uint32_t)aRow * astB + aKb;

    const int l15 = lane & 15;
    const int nIdx = l15 & 7;
    const uint32_t bKb = (uint32_t)(l15 >> 3) * 16;
    const uint32_t bHi = sb + bHiOff + (uint32_t)(colBase + nIdx) * bstB + bKb;
    const uint32_t bLo = sb + bLoOff + (uint32_t)(colBase + nIdx) * bstB + bKb;

#pragma unroll
    for (int k = 0; k < NK; k++) {
        uint32_t ah0, ah1, ah2, ah3, al0, al1, al2, al3;
        LDSM_X4(ah0, ah1, ah2, ah3, aHi + k * 32);
        LDSM_X4(al0, al1, al2, al3, aLo + k * 32);
#pragma unroll
        for (int j = 0; j < NT; j++) {
            uint32_t bh0, bh1, bl0, bl1;
            LDSM_X2(bh0, bh1, bHi + j * 8 * bstB + k * 32);
            LDSM_X2(bl0, bl1, bLo + j * 8 * bstB + k * 32);
            MMA_BF16(c[j], ah0, ah1, ah2, ah3, bh0, bh1);
            MMA_BF16(c[j], ah0, ah1, ah2, ah3, bl0, bl1);
            MMA_BF16(c[j], al0, al1, al2, al3, bh0, bh1);
        }
    }
}

// Epilogue (32 cols per warp): bias + ReLU + split -> act smem (stride 272)
__device__ __forceinline__ void epi128(char* smem, float c[][4],
                                       uint32_t biasOff, uint32_t hiOff, uint32_t loOff,
                                       int lane, int wm, int colBase) {
    int r0 = wm * 16 + (lane >> 2);
#pragma unroll
    for (int t = 0; t < 4; t++) {
        int n0 = colBase + t * 8 + (lane & 3) * 2;
        float2 bb = *(const float2*)(smem + biasOff + n0 * 4);
        {
            float v0 = fmaxf(c[t][0] + bb.x, 0.f);
            float v1 = fmaxf(c[t][1] + bb.y, 0.f);
            uint32_t hi, lo;
            split2(v0, v1, hi, lo);
            uint32_t o = (uint32_t)r0 * AST + (uint32_t)n0 * 2;
            *(uint32_t*)(smem + hiOff + o) = hi;
            *(uint32_t*)(smem + loOff + o) = lo;
        }
        {
            float v0 = fmaxf(c[t][2] + bb.x, 0.f);
            float v1 = fmaxf(c[t][3] + bb.y, 0.f);
            uint32_t hi, lo;
            split2(v0, v1, hi, lo);
            uint32_t o = (uint32_t)(r0 + 8) * AST + (uint32_t)n0 * 2;
            *(uint32_t*)(smem + hiOff + o) = hi;
            *(uint32_t*)(smem + loOff + o) = lo;
        }
    }
}

// ---------------------------------------------------------------------------
// Gather: input tile -> (xHi,xLo) [row][k], stride 272. tg/nthr = thread subset.
// ---------------------------------------------------------------------------
template <int MODE>
__device__ __forceinline__ void do_gather(char* smem,
                                          const float* __restrict__ in,
                                          const float* __restrict__ prev,
                                          int row0, int logn, int off,
                                          uint32_t xHi, uint32_t xLo,
                                          int tg, int nthr) {
    if (MODE == 0) {
        const float2* src = (const float2*)(in + (size_t)row0 * FD);
        for (int i = tg; i < TILE_R * 16; i += nthr) {
            int r = i >> 4, cp = i & 15;
            float2 v = src[i];
            uint32_t hi, lo;
            split2(v.x, v.y, hi, lo);
            uint32_t o = (uint32_t)r * AST + (uint32_t)cp * 4;
            *(uint32_t*)(smem + xHi + o) = hi;
            *(uint32_t*)(smem + xLo + o) = lo;
        }
    } else {
        const int n = 1 << logn;
        for (int i = tg; i < TILE_R * 48; i += nthr) {
            int r = i / 48, cp = i - r * 48;
            int gr = row0 + r;
            int b = gr >> logn, ii = gr & (n - 1);
            float2 v;
            if (cp < 16)
                v = *(const float2*)(in + (((size_t)b * (NLEAF - 1) + off + ii) << 5) + cp * 2);
            else
                v = *(const float2*)(prev + (((size_t)(b << (logn + 1)) + 2 * ii) << 5) + (cp * 2 - 32));
            uint32_t hi, lo;
            split2(v.x, v.y, hi, lo);
            uint32_t o = (uint32_t)r * AST + (uint32_t)cp * 4;
            *(uint32_t*)(smem + xHi + o) = hi;
            *(uint32_t*)(smem + xLo + o) = lo;
        }
    }
}

// ---------------------------------------------------------------------------
// MODE: 0 = leaf (in -> bufA), 1 = join A->B, 2 = join B->A
// ---------------------------------------------------------------------------
template <int NK1, int MODE>
__global__ void __launch_bounds__(THREADS, 1)
level_kernel(const float* __restrict__ in,
             const float* __restrict__ W1, const float* __restrict__ b1,
             const float* __restrict__ W2, const float* __restrict__ b2,
             const float* __restrict__ W3, const float* __restrict__ b3,
             int logn, int off, int ntiles) {
    extern __shared__ char smem[];
    uint32_t sb = smem_u32(smem);
    const int tid = threadIdx.x;
    const int lane = tid & 31;
    const int wid = tid >> 5;
    const int wm = wid & 3;        // row group (16 rows)
    const int wn = wid >> 2;       // col group (32 cols L1/L2; 16 outs L3)
    const int K1 = NK1 * 16;

    // --- stage weights (transposed [N][K], hi/lo) + biases ---
    for (int i = tid; i < K1 * HD; i += THREADS) {
        int k = i / HD, n = i - k * HD;
        float v = W1[i];
        __nv_bfloat16 h = __float2bfloat16(v);
        __nv_bfloat16 l = __float2bfloat16(v - __bfloat162float(h));
        uint32_t o = (uint32_t)n * W1ST + (uint32_t)k * 2;
        *(__nv_bfloat16*)(smem + W1T_HI + o) = h;
        *(__nv_bfloat16*)(smem + W1T_LO + o) = l;
    }
    for (int i = tid; i < HD * HD; i += THREADS) {
        int k = i / HD, n = i - k * HD;
        float v = W2[i];
        __nv_bfloat16 h = __float2bfloat16(v);
        __nv_bfloat16 l = __float2bfloat16(v - __bfloat162float(h));
        uint32_t o = (uint32_t)n * W2ST + (uint32_t)k * 2;
        *(__nv_bfloat16*)(smem + W2T_HI + o) = h;
        *(__nv_bfloat16*)(smem + W2T_LO + o) = l;
    }
    for (int i = tid; i < HD * OD; i += THREADS) {
        int k = i / OD, n = i - k * OD;
        float v = W3[i];
        __nv_bfloat16 h = __float2bfloat16(v);
        __nv_bfloat16 l = __float2bfloat16(v - __bfloat162float(h));
        uint32_t o = (uint32_t)n * W3ST + (uint32_t)k * 2;
        *(__nv_bfloat16*)(smem + W3T_HI + o) = h;
        *(__nv_bfloat16*)(smem + W3T_LO + o) = l;
    }
    if (tid < HD) {
        ((float*)(smem + B1OFF))[tid] = b1[tid];
        ((float*)(smem + B2OFF))[tid] = b2[tid];
    }
    if (tid < OD) ((float*)(smem + B3OFF))[tid] = b3[tid];
    __syncthreads();

    const float* prev = (MODE == 1) ? g_bufA : g_bufB;
    float* dst = (MODE == 0) ? g_bufA : ((MODE == 1) ? g_bufB : g_bufA);
    const int G = gridDim.x;

    // prologue: gather first tile into U (parity 0), all threads
    if (blockIdx.x < ntiles)
        do_gather<MODE>(smem, in, prev, blockIdx.x * TILE_R, logn, off,
                        U_HI, U_LO, tid, THREADS);
    __syncthreads();

    int p = 0;
    for (int t = blockIdx.x; t < ntiles; t += G, p ^= 1) {
        const int row0 = t * TILE_R;
        const uint32_t xHi = p ? V_HI : U_HI;   // X lives here; H2 returns here
        const uint32_t xLo = p ? V_LO : U_LO;
        const uint32_t hHi = p ? U_HI : V_HI;   // H1 here; next X gathered here
        const uint32_t hLo = p ? U_LO : V_LO;

        // ---- layer 1: X[64 x K1] @ W1T -> H1 ----
        {
            float c[4][4];
            gemm3_x4<2, NK1>(sb, xHi, xLo, AST, W1T_HI, W1T_LO, W1ST,
                             wn * 32, lane, wm, c);
            epi128(smem, c, B1OFF, hHi, hLo, lane, wm, wn * 32);
        }
        __syncthreads();

        // ---- layer 2: H1[64 x 128] @ W2T -> H2 (into X's buffer) ----
        {
            float c[4][4];
            gemm3_x4<2, 8>(sb, hHi, hLo, AST, W2T_HI, W2T_LO, W2ST,
                           wn * 32, lane, wm, c);
            epi128(smem, c, B2OFF, xHi, xLo, lane, wm, wn * 32);
        }
        __syncthreads();

        // ---- layer 3 (warps 0-7, as in R4) || gather next (warps 8-15) ----
        if (wn < 2) {
            float c[2][4];
            gemm3_x2<2, 8>(sb, xHi, xLo, AST, W3T_HI, W3T_LO, W3ST,
                           wn * 16, lane, wm, c);
            int r0 = row0 + wm * 16 + (lane >> 2);
#pragma unroll
            for (int tt = 0; tt < 2; tt++) {
                int n0 = wn * 16 + tt * 8 + (lane & 3) * 2;
                float2 bb = *(const float2*)(smem + B3OFF + n0 * 4);
                float2 v0 = make_float2(c[tt][0] + bb.x, c[tt][1] + bb.y);
                float2 v1 = make_float2(c[tt][2] + bb.x, c[tt][3] + bb.y);
                *(float2*)(dst + (size_t)r0 * OD + n0) = v0;
                *(float2*)(dst + (size_t)(r0 + 8) * OD + n0) = v1;
            }
        } else {
            int tn = t + G;
            if (tn < ntiles)
                do_gather<MODE>(smem, in, prev, tn * TILE_R, logn, off,
                                hHi, hLo, tid - 256, 256);
        }
        __syncthreads();
    }
}

// ---------------------------------------------------------------------------
__global__ void extract_kernel(float* __restrict__ out) {
    int b = blockIdx.x * blockDim.x + threadIdx.x;
    if (b < NB) out[b] = g_bufA[(size_t)b * OD];
}

// ---------------------------------------------------------------------------
extern "C" void kernel_launch(void* const* d_in, const int* in_sizes, int n_in,
                              void* d_out, int out_size) {
    const float* leaf_feats = (const float*)d_in[0];
    const float* internal   = (const float*)d_in[1];
    const float* sW1 = (const float*)d_in[2];
    const float* sb1 = (const float*)d_in[3];
    const float* sW2 = (const float*)d_in[4];
    const float* sb2 = (const float*)d_in[5];
    const float* sW3 = (const float*)d_in[6];
    const float* sb3 = (const float*)d_in[7];
    const float* jW1 = (const float*)d_in[8];
    const float* jb1 = (const float*)d_in[9];
    const float* jW2 = (const float*)d_in[10];
    const float* jb2 = (const float*)d_in[11];
    const float* jW3 = (const float*)d_in[12];
    const float* jb3 = (const float*)d_in[13];
    float* out = (float*)d_out;

    cudaFuncSetAttribute(level_kernel<2, 0>, cudaFuncAttributeMaxDynamicSharedMemorySize, SMEM_TOTAL);
    cudaFuncSetAttribute(level_kernel<6, 1>, cudaFuncAttributeMaxDynamicSharedMemorySize, SMEM_TOTAL);
    cudaFuncSetAttribute(level_kernel<6, 2>, cudaFuncAttributeMaxDynamicSharedMemorySize, SMEM_TOTAL);

    // Leaf level: K1 = 32, dst = bufA
    {
        int ntiles = (NB * NLEAF) / TILE_R;     // 32768
        int grid = ntiles < 148 ? ntiles : 148;
        level_kernel<2, 0><<<grid, THREADS, SMEM_TOTAL>>>(
            leaf_feats, sW1, sb1, sW2, sb2, sW3, sb3, 0, 0, ntiles);
    }

    // Join levels n = 512..1; alternate A->B / B->A; final lands in bufA
    int off = 0;
    int mode = 1;
    for (int logn = 9; logn >= 0; --logn) {
        int n = 1 << logn;
        int ntiles = (NB * n) / TILE_R;
        int grid = ntiles < 148 ? ntiles : 148;
        if (mode == 1)
            level_kernel<6, 1><<<grid, THREADS, SMEM_TOTAL>>>(
                internal, jW1, jb1, jW2, jb2, jW3, jb3, logn, off, ntiles);
        else
            level_kernel<6, 2><<<grid, THREADS, SMEM_TOTAL>>>(
                internal, jW1, jb1, jW2, jb2, jW3, jb3, logn, off, ntiles);
        off += n;
        mode = (mode == 1) ? 2 : 1;
    }

    extract_kernel<<<(NB + 255) / 256, 256>>>(out);
}

// round 11
// speedup vs baseline: 1.3564x; 1.3558x over previous
#include <cuda_runtime.h>
#include <cuda_bf16.h>
#include <cstdint>

// ---------------------------------------------------------------------------
// PlanStructuredNetwork via mma.sync bf16 (fp32 acc), bf16x3 split.
// R11 = R4 inner loops (proven best) + hidden gather under L3, with the
// gather loop trip count made COMPILE-TIME (template NTHR) so it unrolls
// and keeps MLP high — the missing piece that sank R8/R9/R10 (runtime nthr
// -> no unroll -> serial 600-cyc LDG chains).
//   Leaf:  (B*1024, 32) -> 128 -> 128 -> 32
//   Join x10: (B*n, 96) -> 128 -> 128 -> 32,  n = 512..1
// ---------------------------------------------------------------------------

#define NB    2048
#define NLEAF 1024
#define FD    32
#define HD    128
#define OD    32

#define TILE_R  64
#define THREADS 512

__device__ float g_bufA[(size_t)NB * NLEAF * OD];        // 268 MB
__device__ float g_bufB[(size_t)NB * (NLEAF / 2) * OD];  // 134 MB

// --- smem byte offsets ---
// Two act buffers U,V; each 64 rows * 272 B, hi+lo planes. Roles cycle by
// tile parity: X in buf[p]; H1 -> buf[1-p]; H2 -> buf[p] (X dead);
// L3 reads buf[p] while warps 8-15 gather next X -> buf[1-p] (H1 dead).
#define U_HI    0
#define U_LO    17408
#define V_HI    34816
#define V_LO    52224
#define W1T_HI  69632       // [128][104] bf16, stride 208
#define W1T_LO  96256
#define W2T_HI  122880      // [128][136] bf16, stride 272
#define W2T_LO  157696
#define W3T_HI  192512      // [32][136] bf16, stride 272
#define W3T_LO  201216
#define B1OFF   209920
#define B2OFF   210432
#define B3OFF   210944
#define SMEM_TOTAL 211072

#define AST     272         // activation row stride (136 bf16, conflict-free)
#define W1ST    208
#define W2ST    272
#define W3ST    272

// ---------------------------------------------------------------------------
__device__ __forceinline__ uint32_t smem_u32(const void* p) {
    uint32_t a;
    asm("{ .reg .u64 t; cvta.to.shared.u64 t, %1; cvt.u32.u64 %0, t; }"
        : "=r"(a) : "l"(p));
    return a;
}

#define LDSM_X4(r0, r1, r2, r3, addr)                                          \
    asm volatile("ldmatrix.sync.aligned.m8n8.x4.shared.b16 {%0,%1,%2,%3}, [%4];" \
                 : "=r"(r0), "=r"(r1), "=r"(r2), "=r"(r3) : "r"(addr))

#define LDSM_X2(r0, r1, addr)                                                  \
    asm volatile("ldmatrix.sync.aligned.m8n8.x2.shared.b16 {%0,%1}, [%2];"     \
                 : "=r"(r0), "=r"(r1) : "r"(addr))

#define MMA_BF16(c, a0, a1, a2, a3, b0, b1)                                    \
    asm volatile("mma.sync.aligned.m16n8k16.row.col.f32.bf16.bf16.f32 "        \
                 "{%0,%1,%2,%3}, {%4,%5,%6,%7}, {%8,%9}, {%0,%1,%2,%3};"       \
                 : "+f"((c)[0]), "+f"((c)[1]), "+f"((c)[2]), "+f"((c)[3])      \
                 : "r"(a0), "r"(a1), "r"(a2), "r"(a3), "r"(b0), "r"(b1))

__device__ __forceinline__ void split2(float v0, float v1, uint32_t& hi, uint32_t& lo) {
    __nv_bfloat16 h0 = __float2bfloat16(v0);
    __nv_bfloat16 h1 = __float2bfloat16(v1);
    float r0 = v0 - __bfloat162float(h0);
    float r1 = v1 - __bfloat162float(h1);
    __nv_bfloat16 l0 = __float2bfloat16(r0);
    __nv_bfloat16 l1 = __float2bfloat16(r1);
    hi = (uint32_t)__bfloat16_as_ushort(h0) | ((uint32_t)__bfloat16_as_ushort(h1) << 16);
    lo = (uint32_t)__bfloat16_as_ushort(l0) | ((uint32_t)__bfloat16_as_ushort(l1) << 16);
}

// ---------------------------------------------------------------------------
// L1/L2 GEMM — EXACT R4 loop: warp = 16 rows x 32 cols, B loaded just-in-time
// per n-pair, 6 MMAs per pair. C = Ahi*Bhi + Ahi*Blo + Alo*Bhi
// ---------------------------------------------------------------------------
template <int NT2, int NK>
__device__ __forceinline__ void gemm3_x4(uint32_t sb,
                                         uint32_t aHiOff, uint32_t aLoOff, int astB,
                                         uint32_t bHiOff, uint32_t bLoOff, int bstB,
                                         int colBase, int lane, int wm,
                                         float c[][4]) {
#pragma unroll
    for (int j = 0; j < 2 * NT2; j++)
#pragma unroll
        for (int q = 0; q < 4; q++) c[j][q] = 0.f;

    const int aRow = wm * 16 + (lane & 15);
    const uint32_t aKb = (uint32_t)(lane >> 4) * 16;
    const uint32_t aHi = sb + aHiOff + (uint32_t)aRow * astB + aKb;
    const uint32_t aLo = sb + aLoOff + (uint32_t)aRow * astB + aKb;

    const int nLoc = (lane & 7) + ((lane >> 4) << 3);
    const uint32_t bKb = (uint32_t)((lane >> 3) & 1) * 16;
    const uint32_t bHi = sb + bHiOff + (uint32_t)(colBase + nLoc) * bstB + bKb;
    const uint32_t bLo = sb + bLoOff + (uint32_t)(colBase + nLoc) * bstB + bKb;

#pragma unroll
    for (int k = 0; k < NK; k++) {
        uint32_t ah0, ah1, ah2, ah3, al0, al1, al2, al3;
        LDSM_X4(ah0, ah1, ah2, ah3, aHi + k * 32);
        LDSM_X4(al0, al1, al2, al3, aLo + k * 32);
#pragma unroll
        for (int j = 0; j < NT2; j++) {
            uint32_t bh0, bh1, bh2, bh3, bl0, bl1, bl2, bl3;
            LDSM_X4(bh0, bh1, bh2, bh3, bHi + j * 16 * bstB + k * 32);
            LDSM_X4(bl0, bl1, bl2, bl3, bLo + j * 16 * bstB + k * 32);
            MMA_BF16(c[2 * j],     ah0, ah1, ah2, ah3, bh0, bh1);
            MMA_BF16(c[2 * j + 1], ah0, ah1, ah2, ah3, bh2, bh3);
            MMA_BF16(c[2 * j],     ah0, ah1, ah2, ah3, bl0, bl1);
            MMA_BF16(c[2 * j + 1], ah0, ah1, ah2, ah3, bl2, bl3);
            MMA_BF16(c[2 * j],     al0, al1, al2, al3, bh0, bh1);
            MMA_BF16(c[2 * j + 1], al0, al1, al2, al3, bh2, bh3);
        }
    }
}

// L3 GEMM — EXACT R4 loop: warp = 16 rows x 16 cols via x2 B loads.
template <int NT, int NK>
__device__ __forceinline__ void gemm3_x2(uint32_t sb,
                                         uint32_t aHiOff, uint32_t aLoOff, int astB,
                                         uint32_t bHiOff, uint32_t bLoOff, int bstB,
                                         int colBase, int lane, int wm,
                                         float c[][4]) {
#pragma unroll
    for (int j = 0; j < NT; j++)
#pragma unroll
        for (int q = 0; q < 4; q++) c[j][q] = 0.f;

    const int aRow = wm * 16 + (lane & 15);
    const uint32_t aKb = (uint32_t)(lane >> 4) * 16;
    const uint32_t aHi = sb + aHiOff + (uint32_t)aRow * astB + aKb;
    const uint32_t aLo = sb + aLoOff + (uint32_t)aRow * astB + aKb;

    const int l15 = lane & 15;
    const int nIdx = l15 & 7;
    const uint32_t bKb = (uint32_t)(l15 >> 3) * 16;
    const uint32_t bHi = sb + bHiOff + (uint32_t)(colBase + nIdx) * bstB + bKb;
    const uint32_t bLo = sb + bLoOff + (uint32_t)(colBase + nIdx) * bstB + bKb;

#pragma unroll
    for (int k = 0; k < NK; k++) {
        uint32_t ah0, ah1, ah2, ah3, al0, al1, al2, al3;
        LDSM_X4(ah0, ah1, ah2, ah3, aHi + k * 32);
        LDSM_X4(al0, al1, al2, al3, aLo + k * 32);
#pragma unroll
        for (int j = 0; j < NT; j++) {
            uint32_t bh0, bh1, bl0, bl1;
            LDSM_X2(bh0, bh1, bHi + j * 8 * bstB + k * 32);
            LDSM_X2(bl0, bl1, bLo + j * 8 * bstB + k * 32);
            MMA_BF16(c[j], ah0, ah1, ah2, ah3, bh0, bh1);
            MMA_BF16(c[j], ah0, ah1, ah2, ah3, bl0, bl1);
            MMA_BF16(c[j], al0, al1, al2, al3, bh0, bh1);
        }
    }
}

// Epilogue (32 cols per warp): bias + ReLU + split -> act smem (stride 272)
__device__ __forceinline__ void epi128(char* smem, float c[][4],
                                       uint32_t biasOff, uint32_t hiOff, uint32_t loOff,
                                       int lane, int wm, int colBase) {
    int r0 = wm * 16 + (lane >> 2);
#pragma unroll
    for (int t = 0; t < 4; t++) {
        int n0 = colBase + t * 8 + (lane & 3) * 2;
        float2 bb = *(const float2*)(smem + biasOff + n0 * 4);
        {
            float v0 = fmaxf(c[t][0] + bb.x, 0.f);
            float v1 = fmaxf(c[t][1] + bb.y, 0.f);
            uint32_t hi, lo;
            split2(v0, v1, hi, lo);
            uint32_t o = (uint32_t)r0 * AST + (uint32_t)n0 * 2;
            *(uint32_t*)(smem + hiOff + o) = hi;
            *(uint32_t*)(smem + loOff + o) = lo;
        }
        {
            float v0 = fmaxf(c[t][2] + bb.x, 0.f);
            float v1 = fmaxf(c[t][3] + bb.y, 0.f);
            uint32_t hi, lo;
            split2(v0, v1, hi, lo);
            uint32_t o = (uint32_t)(r0 + 8) * AST + (uint32_t)n0 * 2;
            *(uint32_t*)(smem + hiOff + o) = hi;
            *(uint32_t*)(smem + loOff + o) = lo;
        }
    }
}

// ---------------------------------------------------------------------------
// Gather: input tile -> (xHi,xLo) [row][k], stride 272.
// NTHR is a TEMPLATE param so the trip count is compile-time and the loop
// fully unrolls (keeps many LDGs in flight).  tg in [0, NTHR).
// ---------------------------------------------------------------------------
template <int MODE, int NTHR>
__device__ __forceinline__ void do_gather(char* smem,
                                          const float* __restrict__ in,
                                          const float* __restrict__ prev,
                                          int row0, int logn, int off,
                                          uint32_t xHi, uint32_t xLo,
                                          int tg) {
    if (MODE == 0) {
        const float2* src = (const float2*)(in + (size_t)row0 * FD);
#pragma unroll
        for (int i = tg; i < TILE_R * 16; i += NTHR) {
            int r = i >> 4, cp = i & 15;
            float2 v = src[i];
            uint32_t hi, lo;
            split2(v.x, v.y, hi, lo);
            uint32_t o = (uint32_t)r * AST + (uint32_t)cp * 4;
            *(uint32_t*)(smem + xHi + o) = hi;
            *(uint32_t*)(smem + xLo + o) = lo;
        }
    } else {
        const int n = 1 << logn;
#pragma unroll
        for (int i = tg; i < TILE_R * 48; i += NTHR) {
            int r = i / 48, cp = i - r * 48;
            int gr = row0 + r;
            int b = gr >> logn, ii = gr & (n - 1);
            float2 v;
            if (cp < 16)
                v = *(const float2*)(in + (((size_t)b * (NLEAF - 1) + off + ii) << 5) + cp * 2);
            else
                v = *(const float2*)(prev + (((size_t)(b << (logn + 1)) + 2 * ii) << 5) + (cp * 2 - 32));
            uint32_t hi, lo;
            split2(v.x, v.y, hi, lo);
            uint32_t o = (uint32_t)r * AST + (uint32_t)cp * 4;
            *(uint32_t*)(smem + xHi + o) = hi;
            *(uint32_t*)(smem + xLo + o) = lo;
        }
    }
}

// ---------------------------------------------------------------------------
// MODE: 0 = leaf (in -> bufA), 1 = join A->B, 2 = join B->A
// ---------------------------------------------------------------------------
template <int NK1, int MODE>
__global__ void __launch_bounds__(THREADS, 1)
level_kernel(const float* __restrict__ in,
             const float* __restrict__ W1, const float* __restrict__ b1,
             const float* __restrict__ W2, const float* __restrict__ b2,
             const float* __restrict__ W3, const float* __restrict__ b3,
             int logn, int off, int ntiles) {
    extern __shared__ char smem[];
    uint32_t sb = smem_u32(smem);
    const int tid = threadIdx.x;
    const int lane = tid & 31;
    const int wid = tid >> 5;
    const int wm = wid & 3;        // row group (16 rows)
    const int wn = wid >> 2;       // col group (32 cols L1/L2; 16 outs L3)
    const int K1 = NK1 * 16;

    // --- stage weights (transposed [N][K], hi/lo) + biases ---
    for (int i = tid; i < K1 * HD; i += THREADS) {
        int k = i / HD, n = i - k * HD;
        float v = W1[i];
        __nv_bfloat16 h = __float2bfloat16(v);
        __nv_bfloat16 l = __float2bfloat16(v - __bfloat162float(h));
        uint32_t o = (uint32_t)n * W1ST + (uint32_t)k * 2;
        *(__nv_bfloat16*)(smem + W1T_HI + o) = h;
        *(__nv_bfloat16*)(smem + W1T_LO + o) = l;
    }
    for (int i = tid; i < HD * HD; i += THREADS) {
        int k = i / HD, n = i - k * HD;
        float v = W2[i];
        __nv_bfloat16 h = __float2bfloat16(v);
        __nv_bfloat16 l = __float2bfloat16(v - __bfloat162float(h));
        uint32_t o = (uint32_t)n * W2ST + (uint32_t)k * 2;
        *(__nv_bfloat16*)(smem + W2T_HI + o) = h;
        *(__nv_bfloat16*)(smem + W2T_LO + o) = l;
    }
    for (int i = tid; i < HD * OD; i += THREADS) {
        int k = i / OD, n = i - k * OD;
        float v = W3[i];
        __nv_bfloat16 h = __float2bfloat16(v);
        __nv_bfloat16 l = __float2bfloat16(v - __bfloat162float(h));
        uint32_t o = (uint32_t)n * W3ST + (uint32_t)k * 2;
        *(__nv_bfloat16*)(smem + W3T_HI + o) = h;
        *(__nv_bfloat16*)(smem + W3T_LO + o) = l;
    }
    if (tid < HD) {
        ((float*)(smem + B1OFF))[tid] = b1[tid];
        ((float*)(smem + B2OFF))[tid] = b2[tid];
    }
    if (tid < OD) ((float*)(smem + B3OFF))[tid] = b3[tid];
    __syncthreads();

    const float* prev = (MODE == 1) ? g_bufA : g_bufB;
    float* dst = (MODE == 0) ? g_bufA : ((MODE == 1) ? g_bufB : g_bufA);
    const int G = gridDim.x;

    // prologue: gather first tile into U (parity 0), all 512 threads, unrolled
    if (blockIdx.x < ntiles)
        do_gather<MODE, THREADS>(smem, in, prev, blockIdx.x * TILE_R, logn, off,
                                 U_HI, U_LO, tid);
    __syncthreads();

    int p = 0;
    for (int t = blockIdx.x; t < ntiles; t += G, p ^= 1) {
        const int row0 = t * TILE_R;
        const uint32_t xHi = p ? V_HI : U_HI;   // X lives here; H2 returns here
        const uint32_t xLo = p ? V_LO : U_LO;
        const uint32_t hHi = p ? U_HI : V_HI;   // H1 here; next X gathered here
        const uint32_t hLo = p ? U_LO : V_LO;

        // ---- layer 1: X[64 x K1] @ W1T -> H1 ----
        {
            float c[4][4];
            gemm3_x4<2, NK1>(sb, xHi, xLo, AST, W1T_HI, W1T_LO, W1ST,
                             wn * 32, lane, wm, c);
            epi128(smem, c, B1OFF, hHi, hLo, lane, wm, wn * 32);
        }
        __syncthreads();

        // ---- layer 2: H1[64 x 128] @ W2T -> H2 (into X's buffer) ----
        {
            float c[4][4];
            gemm3_x4<2, 8>(sb, hHi, hLo, AST, W2T_HI, W2T_LO, W2ST,
                           wn * 32, lane, wm, c);
            epi128(smem, c, B2OFF, xHi, xLo, lane, wm, wn * 32);
        }
        __syncthreads();

        // ---- layer 3 (warps 0-7) || gather next tile (warps 8-15, unrolled) ----
        if (wn < 2) {
            float c[2][4];
            gemm3_x2<2, 8>(sb, xHi, xLo, AST, W3T_HI, W3T_LO, W3ST,
                           wn * 16, lane, wm, c);
            int r0 = row0 + wm * 16 + (lane >> 2);
#pragma unroll
            for (int tt = 0; tt < 2; tt++) {
                int n0 = wn * 16 + tt * 8 + (lane & 3) * 2;
                float2 bb = *(const float2*)(smem + B3OFF + n0 * 4);
                float2 v0 = make_float2(c[tt][0] + bb.x, c[tt][1] + bb.y);
                float2 v1 = make_float2(c[tt][2] + bb.x, c[tt][3] + bb.y);
                *(float2*)(dst + (size_t)r0 * OD + n0) = v0;
                *(float2*)(dst + (size_t)(r0 + 8) * OD + n0) = v1;
            }
        } else {
            int tn = t + G;
            if (tn < ntiles)
                do_gather<MODE, 256>(smem, in, prev, tn * TILE_R, logn, off,
                                     hHi, hLo, tid - 256);
        }
        __syncthreads();
    }
}

// ---------------------------------------------------------------------------
__global__ void extract_kernel(float* __restrict__ out) {
    int b = blockIdx.x * blockDim.x + threadIdx.x;
    if (b < NB) out[b] = g_bufA[(size_t)b * OD];
}

// ---------------------------------------------------------------------------
extern "C" void kernel_launch(void* const* d_in, const int* in_sizes, int n_in,
                              void* d_out, int out_size) {
    const float* leaf_feats = (const float*)d_in[0];
    const float* internal   = (const float*)d_in[1];
    const float* sW1 = (const float*)d_in[2];
    const float* sb1 = (const float*)d_in[3];
    const float* sW2 = (const float*)d_in[4];
    const float* sb2 = (const float*)d_in[5];
    const float* sW3 = (const float*)d_in[6];
    const float* sb3 = (const float*)d_in[7];
    const float* jW1 = (const float*)d_in[8];
    const float* jb1 = (const float*)d_in[9];
    const float* jW2 = (const float*)d_in[10];
    const float* jb2 = (const float*)d_in[11];
    const float* jW3 = (const float*)d_in[12];
    const float* jb3 = (const float*)d_in[13];
    float* out = (float*)d_out;

    cudaFuncSetAttribute(level_kernel<2, 0>, cudaFuncAttributeMaxDynamicSharedMemorySize, SMEM_TOTAL);
    cudaFuncSetAttribute(level_kernel<6, 1>, cudaFuncAttributeMaxDynamicSharedMemorySize, SMEM_TOTAL);
    cudaFuncSetAttribute(level_kernel<6, 2>, cudaFuncAttributeMaxDynamicSharedMemorySize, SMEM_TOTAL);

    // Leaf level: K1 = 32, dst = bufA
    {
        int ntiles = (NB * NLEAF) / TILE_R;     // 32768
        int grid = ntiles < 148 ? ntiles : 148;
        level_kernel<2, 0><<<grid, THREADS, SMEM_TOTAL>>>(
            leaf_feats, sW1, sb1, sW2, sb2, sW3, sb3, 0, 0, ntiles);
    }

    // Join levels n = 512..1; alternate A->B / B->A; final lands in bufA
    int off = 0;
    int mode = 1;
    for (int logn = 9; logn >= 0; --logn) {
        int n = 1 << logn;
        int ntiles = (NB * n) / TILE_R;
        int grid = ntiles < 148 ? ntiles : 148;
        if (mode == 1)
            level_kernel<6, 1><<<grid, THREADS, SMEM_TOTAL>>>(
                internal, jW1, jb1, jW2, jb2, jW3, jb3, logn, off, ntiles);
        else
            level_kernel<6, 2><<<grid, THREADS, SMEM_TOTAL>>>(
                internal, jW1, jb1, jW2, jb2, jW3, jb3, logn, off, ntiles);
        off += n;
        mode = (mode == 1) ? 2 : 1;
    }

    extract_kernel<<<(NB + 255) / 256, 256>>>(out);
}

// round 13
// speedup vs baseline: 1.3751x; 1.0138x over previous
#include <cuda_runtime.h>
#include <cuda_bf16.h>
#include <cstdint>

// ---------------------------------------------------------------------------
// PlanStructuredNetwork via mma.sync bf16 (fp32 acc), bf16x3 split.
// R12: split-CTA. Two independent groups of 256 threads (warps 0-7 / 8-15),
// each running its OWN 32-row tile stream with named barriers, sharing the
// resident weights. Inner GEMM loops are byte-identical to R4/R11 (proven
// best schedule). Goal: the two phase-shifted streams cover each other's
// epilogue/barrier/gather bubbles and keep the tensor pipe fed.
//   Leaf:  (B*1024, 32) -> 128 -> 128 -> 32
//   Join x10: (B*n, 96) -> 128 -> 128 -> 32,  n = 512..1
// ---------------------------------------------------------------------------

#define NB    2048
#define NLEAF 1024
#define FD    32
#define HD    128
#define OD    32

#define TILE_R  32          // per-group tile
#define THREADS 512
#define GTHREADS 256        // threads per group

__device__ float g_bufA[(size_t)NB * NLEAF * OD];        // 268 MB
__device__ float g_bufB[(size_t)NB * (NLEAF / 2) * OD];  // 134 MB

// --- smem byte offsets ---
// Per-group act buffers: X (32x272, hi+lo) + H (32x272, hi+lo) = 34816 B.
// Group 0 at 0, group 1 at 34816. Weights shared (same offsets as R4/R11).
#define GRP_STRIDE 34816
#define X_HI_OFF 0
#define X_LO_OFF 8704
#define H_HI_OFF 17408
#define H_LO_OFF 26112

#define W1T_HI  69632       // [128][104] bf16, stride 208
#define W1T_LO  96256
#define W2T_HI  122880      // [128][136] bf16, stride 272
#define W2T_LO  157696
#define W3T_HI  192512      // [32][136] bf16, stride 272
#define W3T_LO  201216
#define B1OFF   209920
#define B2OFF   210432
#define B3OFF   210944
#define SMEM_TOTAL 211072

#define AST     272         // activation row stride (136 bf16, conflict-free)
#define W1ST    208
#define W2ST    272
#define W3ST    272

// ---------------------------------------------------------------------------
__device__ __forceinline__ uint32_t smem_u32(const void* p) {
    uint32_t a;
    asm("{ .reg .u64 t; cvta.to.shared.u64 t, %1; cvt.u32.u64 %0, t; }"
        : "=r"(a) : "l"(p));
    return a;
}

// named barrier: group g (256 threads) uses id g+1
#define BAR_GRP(id) \
    asm volatile("bar.sync %0, %1;" :: "r"(id), "n"(GTHREADS) : "memory")

#define LDSM_X4(r0, r1, r2, r3, addr)                                          \
    asm volatile("ldmatrix.sync.aligned.m8n8.x4.shared.b16 {%0,%1,%2,%3}, [%4];" \
                 : "=r"(r0), "=r"(r1), "=r"(r2), "=r"(r3) : "r"(addr))

#define LDSM_X2(r0, r1, addr)                                                  \
    asm volatile("ldmatrix.sync.aligned.m8n8.x2.shared.b16 {%0,%1}, [%2];"     \
                 : "=r"(r0), "=r"(r1) : "r"(addr))

#define MMA_BF16(c, a0, a1, a2, a3, b0, b1)                                    \
    asm volatile("mma.sync.aligned.m16n8k16.row.col.f32.bf16.bf16.f32 "        \
                 "{%0,%1,%2,%3}, {%4,%5,%6,%7}, {%8,%9}, {%0,%1,%2,%3};"       \
                 : "+f"((c)[0]), "+f"((c)[1]), "+f"((c)[2]), "+f"((c)[3])      \
                 : "r"(a0), "r"(a1), "r"(a2), "r"(a3), "r"(b0), "r"(b1))

__device__ __forceinline__ void split2(float v0, float v1, uint32_t& hi, uint32_t& lo) {
    __nv_bfloat16 h0 = __float2bfloat16(v0);
    __nv_bfloat16 h1 = __float2bfloat16(v1);
    float r0 = v0 - __bfloat162float(h0);
    float r1 = v1 - __bfloat162float(h1);
    __nv_bfloat16 l0 = __float2bfloat16(r0);
    __nv_bfloat16 l1 = __float2bfloat16(r1);
    hi = (uint32_t)__bfloat16_as_ushort(h0) | ((uint32_t)__bfloat16_as_ushort(h1) << 16);
    lo = (uint32_t)__bfloat16_as_ushort(l0) | ((uint32_t)__bfloat16_as_ushort(l1) << 16);
}

// ---------------------------------------------------------------------------
// L1/L2 GEMM — EXACT R4 loop: warp = 16 rows x 32 cols, B loaded just-in-time
// per n-pair, 6 MMAs per pair. C = Ahi*Bhi + Ahi*Blo + Alo*Bhi
// ---------------------------------------------------------------------------
template <int NT2, int NK>
__device__ __forceinline__ void gemm3_x4(uint32_t sb,
                                         uint32_t aHiOff, uint32_t aLoOff, int astB,
                                         uint32_t bHiOff, uint32_t bLoOff, int bstB,
                                         int colBase, int lane, int wm,
                                         float c[][4]) {
#pragma unroll
    for (int j = 0; j < 2 * NT2; j++)
#pragma unroll
        for (int q = 0; q < 4; q++) c[j][q] = 0.f;

    const int aRow = wm * 16 + (lane & 15);
    const uint32_t aKb = (uint32_t)(lane >> 4) * 16;
    const uint32_t aHi = sb + aHiOff + (uint32_t)aRow * astB + aKb;
    const uint32_t aLo = sb + aLoOff + (uint32_t)aRow * astB + aKb;

    const int nLoc = (lane & 7) + ((lane >> 4) << 3);
    const uint32_t bKb = (uint32_t)((lane >> 3) & 1) * 16;
    const uint32_t bHi = sb + bHiOff + (uint32_t)(colBase + nLoc) * bstB + bKb;
    const uint32_t bLo = sb + bLoOff + (uint32_t)(colBase + nLoc) * bstB + bKb;

#pragma unroll
    for (int k = 0; k < NK; k++) {
        uint32_t ah0, ah1, ah2, ah3, al0, al1, al2, al3;
        LDSM_X4(ah0, ah1, ah2, ah3, aHi + k * 32);
        LDSM_X4(al0, al1, al2, al3, aLo + k * 32);
#pragma unroll
        for (int j = 0; j < NT2; j++) {
            uint32_t bh0, bh1, bh2, bh3, bl0, bl1, bl2, bl3;
            LDSM_X4(bh0, bh1, bh2, bh3, bHi + j * 16 * bstB + k * 32);
            LDSM_X4(bl0, bl1, bl2, bl3, bLo + j * 16 * bstB + k * 32);
            MMA_BF16(c[2 * j],     ah0, ah1, ah2, ah3, bh0, bh1);
            MMA_BF16(c[2 * j + 1], ah0, ah1, ah2, ah3, bh2, bh3);
            MMA_BF16(c[2 * j],     ah0, ah1, ah2, ah3, bl0, bl1);
            MMA_BF16(c[2 * j + 1], ah0, ah1, ah2, ah3, bl2, bl3);
            MMA_BF16(c[2 * j],     al0, al1, al2, al3, bh0, bh1);
            MMA_BF16(c[2 * j + 1], al0, al1, al2, al3, bh2, bh3);
        }
    }
}

// L3 GEMM — R4 x2 loop, NT=1: warp = 16 rows x 8 cols.
template <int NT, int NK>
__device__ __forceinline__ void gemm3_x2(uint32_t sb,
                                         uint32_t aHiOff, uint32_t aLoOff, int astB,
                                         uint32_t bHiOff, uint32_t bLoOff, int bstB,
                                         int colBase, int lane, int wm,
                                         float c[][4]) {
#pragma unroll
    for (int j = 0; j < NT; j++)
#pragma unroll
        for (int q = 0; q < 4; q++) c[j][q] = 0.f;

    const int aRow = wm * 16 + (lane & 15);
    const uint32_t aKb = (uint32_t)(lane >> 4) * 16;
    const uint32_t aHi = sb + aHiOff + (uint32_t)aRow * astB + aKb;
    const uint32_t aLo = sb + aLoOff + (uint32_t)aRow * astB + aKb;

    const int l15 = lane & 15;
    const int nIdx = l15 & 7;
    const uint32_t bKb = (uint32_t)(l15 >> 3) * 16;
    const uint32_t bHi = sb + bHiOff + (uint32_t)(colBase + nIdx) * bstB + bKb;
    const uint32_t bLo = sb + bLoOff + (uint32_t)(colBase + nIdx) * bstB + bKb;

#pragma unroll
    for (int k = 0; k < NK; k++) {
        uint32_t ah0, ah1, ah2, ah3, al0, al1, al2, al3;
        LDSM_X4(ah0, ah1, ah2, ah3, aHi + k * 32);
        LDSM_X4(al0, al1, al2, al3, aLo + k * 32);
#pragma unroll
        for (int j = 0; j < NT; j++) {
            uint32_t bh0, bh1, bl0, bl1;
            LDSM_X2(bh0, bh1, bHi + j * 8 * bstB + k * 32);
            LDSM_X2(bl0, bl1, bLo + j * 8 * bstB + k * 32);
            MMA_BF16(c[j], ah0, ah1, ah2, ah3, bh0, bh1);
            MMA_BF16(c[j], ah0, ah1, ah2, ah3, bl0, bl1);
            MMA_BF16(c[j], al0, al1, al2, al3, bh0, bh1);
        }
    }
}

// Epilogue (32 cols per warp): bias + ReLU + split -> act smem (stride 272)
__device__ __forceinline__ void epi128(char* smem, float c[][4],
                                       uint32_t biasOff, uint32_t hiOff, uint32_t loOff,
                                       int lane, int wm, int colBase) {
    int r0 = wm * 16 + (lane >> 2);
#pragma unroll
    for (int t = 0; t < 4; t++) {
        int n0 = colBase + t * 8 + (lane & 3) * 2;
        float2 bb = *(const float2*)(smem + biasOff + n0 * 4);
        {
            float v0 = fmaxf(c[t][0] + bb.x, 0.f);
            float v1 = fmaxf(c[t][1] + bb.y, 0.f);
            uint32_t hi, lo;
            split2(v0, v1, hi, lo);
            uint32_t o = (uint32_t)r0 * AST + (uint32_t)n0 * 2;
            *(uint32_t*)(smem + hiOff + o) = hi;
            *(uint32_t*)(smem + loOff + o) = lo;
        }
        {
            float v0 = fmaxf(c[t][2] + bb.x, 0.f);
            float v1 = fmaxf(c[t][3] + bb.y, 0.f);
            uint32_t hi, lo;
            split2(v0, v1, hi, lo);
            uint32_t o = (uint32_t)(r0 + 8) * AST + (uint32_t)n0 * 2;
            *(uint32_t*)(smem + hiOff + o) = hi;
            *(uint32_t*)(smem + loOff + o) = lo;
        }
    }
}

// ---------------------------------------------------------------------------
// Gather: 32-row tile -> (xHi,xLo), compile-time NTHR for full unroll.
// ---------------------------------------------------------------------------
template <int MODE, int NTHR>
__device__ __forceinline__ void do_gather(char* smem,
                                          const float* __restrict__ in,
                                          const float* __restrict__ prev,
                                          int row0, int logn, int off,
                                          uint32_t xHi, uint32_t xLo,
                                          int tg) {
    if (MODE == 0) {
        const float2* src = (const float2*)(in + (size_t)row0 * FD);
#pragma unroll
        for (int i = tg; i < TILE_R * 16; i += NTHR) {
            int r = i >> 4, cp = i & 15;
            float2 v = src[i];
            uint32_t hi, lo;
            split2(v.x, v.y, hi, lo);
            uint32_t o = (uint32_t)r * AST + (uint32_t)cp * 4;
            *(uint32_t*)(smem + xHi + o) = hi;
            *(uint32_t*)(smem + xLo + o) = lo;
        }
    } else {
        const int n = 1 << logn;
#pragma unroll
        for (int i = tg; i < TILE_R * 48; i += NTHR) {
            int r = i / 48, cp = i - r * 48;
            int gr = row0 + r;
            int b = gr >> logn, ii = gr & (n - 1);
            float2 v;
            if (cp < 16)
                v = *(const float2*)(in + (((size_t)b * (NLEAF - 1) + off + ii) << 5) + cp * 2);
            else
                v = *(const float2*)(prev + (((size_t)(b << (logn + 1)) + 2 * ii) << 5) + (cp * 2 - 32));
            uint32_t hi, lo;
            split2(v.x, v.y, hi, lo);
            uint32_t o = (uint32_t)r * AST + (uint32_t)cp * 4;
            *(uint32_t*)(smem + xHi + o) = hi;
            *(uint32_t*)(smem + xLo + o) = lo;
        }
    }
}

// ---------------------------------------------------------------------------
// MODE: 0 = leaf (in -> bufA), 1 = join A->B, 2 = join B->A
// Two groups of 256 threads run independent tile streams.
// ---------------------------------------------------------------------------
template <int NK1, int MODE>
__global__ void __launch_bounds__(THREADS, 1)
level_kernel(const float* __restrict__ in,
             const float* __restrict__ W1, const float* __restrict__ b1,
             const float* __restrict__ W2, const float* __restrict__ b2,
             const float* __restrict__ W3, const float* __restrict__ b3,
             int logn, int off, int ntiles) {
    extern __shared__ char smem[];
    uint32_t sb = smem_u32(smem);
    const int tid = threadIdx.x;
    const int K1 = NK1 * 16;

    // --- stage weights (transposed [N][K], hi/lo) + biases (all 512 thr) ---
    for (int i = tid; i < K1 * HD; i += THREADS) {
        int k = i / HD, n = i - k * HD;
        float v = W1[i];
        __nv_bfloat16 h = __float2bfloat16(v);
        __nv_bfloat16 l = __float2bfloat16(v - __bfloat162float(h));
        uint32_t o = (uint32_t)n * W1ST + (uint32_t)k * 2;
        *(__nv_bfloat16*)(smem + W1T_HI + o) = h;
        *(__nv_bfloat16*)(smem + W1T_LO + o) = l;
    }
    for (int i = tid; i < HD * HD; i += THREADS) {
        int k = i / HD, n = i - k * HD;
        float v = W2[i];
        __nv_bfloat16 h = __float2bfloat16(v);
        __nv_bfloat16 l = __float2bfloat16(v - __bfloat162float(h));
        uint32_t o = (uint32_t)n * W2ST + (uint32_t)k * 2;
        *(__nv_bfloat16*)(smem + W2T_HI + o) = h;
        *(__nv_bfloat16*)(smem + W2T_LO + o) = l;
    }
    for (int i = tid; i < HD * OD; i += THREADS) {
        int k = i / OD, n = i - k * OD;
        float v = W3[i];
        __nv_bfloat16 h = __float2bfloat16(v);
        __nv_bfloat16 l = __float2bfloat16(v - __bfloat162float(h));
        uint32_t o = (uint32_t)n * W3ST + (uint32_t)k * 2;
        *(__nv_bfloat16*)(smem + W3T_HI + o) = h;
        *(__nv_bfloat16*)(smem + W3T_LO + o) = l;
    }
    if (tid < HD) {
        ((float*)(smem + B1OFF))[tid] = b1[tid];
        ((float*)(smem + B2OFF))[tid] = b2[tid];
    }
    if (tid < OD) ((float*)(smem + B3OFF))[tid] = b3[tid];
    __syncthreads();

    // --- group decomposition ---
    const int grp = tid >> 8;            // 0 or 1
    const int gtid = tid & 255;          // thread within group
    const int gwid = gtid >> 5;          // warp within group: 0..7
    const int lane = tid & 31;
    const int wm = gwid & 1;             // row group (2 x 16 = 32 rows)
    const int wn = gwid >> 1;            // col group (4 x 32 = 128 cols)
    const int barid = grp + 1;           // named barrier id

    const uint32_t gbase = (uint32_t)grp * GRP_STRIDE;
    const uint32_t xHi = gbase + X_HI_OFF, xLo = gbase + X_LO_OFF;
    const uint32_t hHi = gbase + H_HI_OFF, hLo = gbase + H_LO_OFF;

    const float* prev = (MODE == 1) ? g_bufA : g_bufB;
    float* dst = (MODE == 0) ? g_bufA : ((MODE == 1) ? g_bufB : g_bufA);
    const int step = 2 * gridDim.x;

    for (int t = 2 * blockIdx.x + grp; t < ntiles; t += step) {
        const int row0 = t * TILE_R;

        // ---- gather (group-local, unrolled) ----
        do_gather<MODE, GTHREADS>(smem, in, prev, row0, logn, off, xHi, xLo, gtid);
        BAR_GRP(barid);

        // ---- layer 1: X[32 x K1] @ W1T -> H ----
        {
            float c[4][4];
            gemm3_x4<2, NK1>(sb, xHi, xLo, AST, W1T_HI, W1T_LO, W1ST,
                             wn * 32, lane, wm, c);
            epi128(smem, c, B1OFF, hHi, hLo, lane, wm, wn * 32);
        }
        BAR_GRP(barid);

        // ---- layer 2: H[32 x 128] @ W2T -> X (X dead) ----
        {
            float c[4][4];
            gemm3_x4<2, 8>(sb, hHi, hLo, AST, W2T_HI, W2T_LO, W2ST,
                           wn * 32, lane, wm, c);
            epi128(smem, c, B2OFF, xHi, xLo, lane, wm, wn * 32);
        }
        BAR_GRP(barid);

        // ---- layer 3: X[32 x 128] @ W3T -> gmem fp32 [32 x 32] ----
        {
            float c[1][4];
            gemm3_x2<1, 8>(sb, xHi, xLo, AST, W3T_HI, W3T_LO, W3ST,
                           wn * 8, lane, wm, c);
            int r0 = row0 + wm * 16 + (lane >> 2);
            int n0 = wn * 8 + (lane & 3) * 2;
            float2 bb = *(const float2*)(smem + B3OFF + n0 * 4);
            float2 v0 = make_float2(c[0][0] + bb.x, c[0][1] + bb.y);
            float2 v1 = make_float2(c[0][2] + bb.x, c[0][3] + bb.y);
            *(float2*)(dst + (size_t)r0 * OD + n0) = v0;
            *(float2*)(dst + (size_t)(r0 + 8) * OD + n0) = v1;
        }
        BAR_GRP(barid);
    }
}

// ---------------------------------------------------------------------------
__global__ void extract_kernel(float* __restrict__ out) {
    int b = blockIdx.x * blockDim.x + threadIdx.x;
    if (b < NB) out[b] = g_bufA[(size_t)b * OD];
}

// ---------------------------------------------------------------------------
extern "C" void kernel_launch(void* const* d_in, const int* in_sizes, int n_in,
                              void* d_out, int out_size) {
    const float* leaf_feats = (const float*)d_in[0];
    const float* internal   = (const float*)d_in[1];
    const float* sW1 = (const float*)d_in[2];
    const float* sb1 = (const float*)d_in[3];
    const float* sW2 = (const float*)d_in[4];
    const float* sb2 = (const float*)d_in[5];
    const float* sW3 = (const float*)d_in[6];
    const float* sb3 = (const float*)d_in[7];
    const float* jW1 = (const float*)d_in[8];
    const float* jb1 = (const float*)d_in[9];
    const float* jW2 = (const float*)d_in[10];
    const float* jb2 = (const float*)d_in[11];
    const float* jW3 = (const float*)d_in[12];
    const float* jb3 = (const float*)d_in[13];
    float* out = (float*)d_out;

    cudaFuncSetAttribute(level_kernel<2, 0>, cudaFuncAttributeMaxDynamicSharedMemorySize, SMEM_TOTAL);
    cudaFuncSetAttribute(level_kernel<6, 1>, cudaFuncAttributeMaxDynamicSharedMemorySize, SMEM_TOTAL);
    cudaFuncSetAttribute(level_kernel<6, 2>, cudaFuncAttributeMaxDynamicSharedMemorySize, SMEM_TOTAL);

    // Leaf level: K1 = 32, dst = bufA
    {
        int ntiles = (NB * NLEAF) / TILE_R;     // 65536
        int pairs = ntiles / 2;
        int grid = pairs < 148 ? pairs : 148;
        level_kernel<2, 0><<<grid, THREADS, SMEM_TOTAL>>>(
            leaf_feats, sW1, sb1, sW2, sb2, sW3, sb3, 0, 0, ntiles);
    }

    // Join levels n = 512..1; alternate A->B / B->A; final lands in bufA
    int off = 0;
    int mode = 1;
    for (int logn = 9; logn >= 0; --logn) {
        int n = 1 << logn;
        int ntiles = (NB * n) / TILE_R;
        int pairs = (ntiles + 1) / 2;
        int grid = pairs < 148 ? pairs : 148;
        if (mode == 1)
            level_kernel<6, 1><<<grid, THREADS, SMEM_TOTAL>>>(
                internal, jW1, jb1, jW2, jb2, jW3, jb3, logn, off, ntiles);
        else
            level_kernel<6, 2><<<grid, THREADS, SMEM_TOTAL>>>(
                internal, jW1, jb1, jW2, jb2, jW3, jb3, logn, off, ntiles);
        off += n;
        mode = (mode == 1) ? 2 : 1;
    }

    extract_kernel<<<(NB + 255) / 256, 256>>>(out);
}

// round 14
// speedup vs baseline: 1.4102x; 1.0255x over previous
#include <cuda_runtime.h>
#include <cuda_bf16.h>
#include <cstdint>

// ---------------------------------------------------------------------------
// PlanStructuredNetwork via mma.sync bf16 (fp32 acc), bf16x3 split.
// R14 = R12 split-CTA structure + W1/W2 B-operands served as PRE-FRAGMENTED
// gmem arrays via one coalesced LDG.128 per 16-col tile (prep kernel runs
// once per launch sequence). Cuts L1/LDSM traffic ~33% on the dominant
// loops and frees smem (weights leave smem; L1D carveout now holds frags).
// W3/L3 keeps the proven smem-LDSM path. Arithmetic bit-identical to R12.
//   Leaf:  (B*1024, 32) -> 128 -> 128 -> 32
//   Join x10: (B*n, 96) -> 128 -> 128 -> 32,  n = 512..1
// ---------------------------------------------------------------------------

#define NB    2048
#define NLEAF 1024
#define FD    32
#define HD    128
#define OD    32

#define TILE_R  32          // per-group tile
#define THREADS 512
#define GTHREADS 256

__device__ float g_bufA[(size_t)NB * NLEAF * OD];        // 268 MB
__device__ float g_bufB[(size_t)NB * (NLEAF / 2) * OD];  // 134 MB

// Frag arrays: layout ((g * NK + kk) * 2 + hl) * 32 + lane, each uint4 =
// (b0,b1,b2,b3) for the 16-col group g, k-chunk kk. hl: 0=hi, 1=lo.
__device__ uint4 g_fragL1[8 * 2 * 2 * 32];   // leaf W1:  K=32  -> NK=2
__device__ uint4 g_fragL2[8 * 8 * 2 * 32];   // leaf W2:  K=128 -> NK=8
__device__ uint4 g_fragJ1[8 * 6 * 2 * 32];   // join W1:  K=96  -> NK=6
__device__ uint4 g_fragJ2[8 * 8 * 2 * 32];   // join W2:  K=128 -> NK=8

// --- smem byte offsets ---
// Per-group act buffers (as R12): X(hi,lo) + H(hi,lo), 32 rows x 272 B.
#define GRP_STRIDE 34816
#define X_HI_OFF 0
#define X_LO_OFF 8704
#define H_HI_OFF 17408
#define H_LO_OFF 26112
// W3 stays in smem (L3 unchanged): [32][272] hi/lo
#define W3T_HI  69632
#define W3T_LO  78336
#define B1OFF   87040
#define B2OFF   87552
#define B3OFF   88064
#define SMEM_TOTAL 88320

#define AST     272
#define W3ST    272

// ---------------------------------------------------------------------------
__device__ __forceinline__ uint32_t smem_u32(const void* p) {
    uint32_t a;
    asm("{ .reg .u64 t; cvta.to.shared.u64 t, %1; cvt.u32.u64 %0, t; }"
        : "=r"(a) : "l"(p));
    return a;
}

#define BAR_GRP(id) \
    asm volatile("bar.sync %0, %1;" :: "r"(id), "n"(GTHREADS) : "memory")

#define LDSM_X4(r0, r1, r2, r3, addr)                                          \
    asm volatile("ldmatrix.sync.aligned.m8n8.x4.shared.b16 {%0,%1,%2,%3}, [%4];" \
                 : "=r"(r0), "=r"(r1), "=r"(r2), "=r"(r3) : "r"(addr))

#define LDSM_X2(r0, r1, addr)                                                  \
    asm volatile("ldmatrix.sync.aligned.m8n8.x2.shared.b16 {%0,%1}, [%2];"     \
                 : "=r"(r0), "=r"(r1) : "r"(addr))

#define MMA_BF16(c, a0, a1, a2, a3, b0, b1)                                    \
    asm volatile("mma.sync.aligned.m16n8k16.row.col.f32.bf16.bf16.f32 "        \
                 "{%0,%1,%2,%3}, {%4,%5,%6,%7}, {%8,%9}, {%0,%1,%2,%3};"       \
                 : "+f"((c)[0]), "+f"((c)[1]), "+f"((c)[2]), "+f"((c)[3])      \
                 : "r"(a0), "r"(a1), "r"(a2), "r"(a3), "r"(b0), "r"(b1))

__device__ __forceinline__ void split2(float v0, float v1, uint32_t& hi, uint32_t& lo) {
    __nv_bfloat16 h0 = __float2bfloat16(v0);
    __nv_bfloat16 h1 = __float2bfloat16(v1);
    float r0 = v0 - __bfloat162float(h0);
    float r1 = v1 - __bfloat162float(h1);
    __nv_bfloat16 l0 = __float2bfloat16(r0);
    __nv_bfloat16 l1 = __float2bfloat16(r1);
    hi = (uint32_t)__bfloat16_as_ushort(h0) | ((uint32_t)__bfloat16_as_ushort(h1) << 16);
    lo = (uint32_t)__bfloat16_as_ushort(l0) | ((uint32_t)__bfloat16_as_ushort(l1) << 16);
}

// ---------------------------------------------------------------------------
// Prep: W [Ktot][128] fp32 row-major -> frag array.
// frag[((g*NK + kk)*2 + hl)*32 + lane] = uint4{x,y,z,w}:
//   x = pair(k0,   n0)   y = pair(k0+8, n0)
//   z = pair(k0,   n0+8) w = pair(k0+8, n0+8)
// n0 = g*16 + (lane>>2), k0 = kk*16 + 2*(lane&3); pair(k,n) packs
// (bf16(W[k][n]), bf16(W[k+1][n])) low/high — identical to the ldmatrix-fed
// operands of the R12 kernel.
// ---------------------------------------------------------------------------
__global__ void prep_frags(const float* __restrict__ W, uint4* __restrict__ frag,
                           int Ktot) {
    const int NK = Ktot / 16;
    int idx = blockIdx.x * blockDim.x + threadIdx.x;
    int total = 8 * NK * 32;
    if (idx >= total) return;
    int lane = idx & 31;
    int kk = (idx >> 5) % NK;
    int g = idx / (32 * NK);
    int n0 = g * 16 + (lane >> 2);
    int k0 = kk * 16 + 2 * (lane & 3);

    uint4 hi4, lo4;
    split2(W[k0 * HD + n0],           W[(k0 + 1) * HD + n0],           hi4.x, lo4.x);
    split2(W[(k0 + 8) * HD + n0],     W[(k0 + 9) * HD + n0],           hi4.y, lo4.y);
    split2(W[k0 * HD + n0 + 8],       W[(k0 + 1) * HD + n0 + 8],       hi4.z, lo4.z);
    split2(W[(k0 + 8) * HD + n0 + 8], W[(k0 + 9) * HD + n0 + 8],       hi4.w, lo4.w);

    int base = ((g * NK + kk) * 2) * 32 + lane;
    frag[base] = hi4;
    frag[base + 32] = lo4;
}

// ---------------------------------------------------------------------------
// L1/L2 GEMM: A via LDSM from act smem (unchanged); B via LDG.128 from frag
// array (hi + lo per k,j). Same MMA order as R12 -> bit-identical results.
// ---------------------------------------------------------------------------
template <int NT2, int NK>
__device__ __forceinline__ void gemm3_frag(uint32_t sb,
                                           uint32_t aHiOff, uint32_t aLoOff,
                                           const uint4* __restrict__ frag,
                                           int colBase, int lane, int wm,
                                           float c[][4]) {
#pragma unroll
    for (int j = 0; j < 2 * NT2; j++)
#pragma unroll
        for (int q = 0; q < 4; q++) c[j][q] = 0.f;

    const int aRow = wm * 16 + (lane & 15);
    const uint32_t aKb = (uint32_t)(lane >> 4) * 16;
    const uint32_t aHi = sb + aHiOff + (uint32_t)aRow * AST + aKb;
    const uint32_t aLo = sb + aLoOff + (uint32_t)aRow * AST + aKb;

    const uint4* fb = frag + (size_t)(colBase >> 4) * NK * 64 + lane;

#pragma unroll
    for (int k = 0; k < NK; k++) {
        uint32_t ah0, ah1, ah2, ah3, al0, al1, al2, al3;
        LDSM_X4(ah0, ah1, ah2, ah3, aHi + k * 32);
        LDSM_X4(al0, al1, al2, al3, aLo + k * 32);
#pragma unroll
        for (int j = 0; j < NT2; j++) {
            const uint4* p = fb + (j * NK + k) * 64;
            uint4 bh = __ldg(p);
            uint4 bl = __ldg(p + 32);
            MMA_BF16(c[2 * j],     ah0, ah1, ah2, ah3, bh.x, bh.y);
            MMA_BF16(c[2 * j + 1], ah0, ah1, ah2, ah3, bh.z, bh.w);
            MMA_BF16(c[2 * j],     ah0, ah1, ah2, ah3, bl.x, bl.y);
            MMA_BF16(c[2 * j + 1], ah0, ah1, ah2, ah3, bl.z, bl.w);
            MMA_BF16(c[2 * j],     al0, al1, al2, al3, bh.x, bh.y);
            MMA_BF16(c[2 * j + 1], al0, al1, al2, al3, bh.z, bh.w);
        }
    }
}

// L3 GEMM — unchanged R12 smem path: warp = 16 rows x 8 cols via x2 B loads.
template <int NT, int NK>
__device__ __forceinline__ void gemm3_x2(uint32_t sb,
                                         uint32_t aHiOff, uint32_t aLoOff, int astB,
                                         uint32_t bHiOff, uint32_t bLoOff, int bstB,
                                         int colBase, int lane, int wm,
                                         float c[][4]) {
#pragma unroll
    for (int j = 0; j < NT; j++)
#pragma unroll
        for (int q = 0; q < 4; q++) c[j][q] = 0.f;

    const int aRow = wm * 16 + (lane & 15);
    const uint32_t aKb = (uint32_t)(lane >> 4) * 16;
    const uint32_t aHi = sb + aHiOff + (uint32_t)aRow * astB + aKb;
    const uint32_t aLo = sb + aLoOff + (uint32_t)aRow * astB + aKb;

    const int l15 = lane & 15;
    const int nIdx = l15 & 7;
    const uint32_t bKb = (uint32_t)(l15 >> 3) * 16;
    const uint32_t bHi = sb + bHiOff + (uint32_t)(colBase + nIdx) * bstB + bKb;
    const uint32_t bLo = sb + bLoOff + (uint32_t)(colBase + nIdx) * bstB + bKb;

#pragma unroll
    for (int k = 0; k < NK; k++) {
        uint32_t ah0, ah1, ah2, ah3, al0, al1, al2, al3;
        LDSM_X4(ah0, ah1, ah2, ah3, aHi + k * 32);
        LDSM_X4(al0, al1, al2, al3, aLo + k * 32);
#pragma unroll
        for (int j = 0; j < NT; j++) {
            uint32_t bh0, bh1, bl0, bl1;
            LDSM_X2(bh0, bh1, bHi + j * 8 * bstB + k * 32);
            LDSM_X2(bl0, bl1, bLo + j * 8 * bstB + k * 32);
            MMA_BF16(c[j], ah0, ah1, ah2, ah3, bh0, bh1);
            MMA_BF16(c[j], ah0, ah1, ah2, ah3, bl0, bl1);
            MMA_BF16(c[j], al0, al1, al2, al3, bh0, bh1);
        }
    }
}

// Epilogue (32 cols per warp): bias + ReLU + split -> act smem (stride 272)
__device__ __forceinline__ void epi128(char* smem, float c[][4],
                                       uint32_t biasOff, uint32_t hiOff, uint32_t loOff,
                                       int lane, int wm, int colBase) {
    int r0 = wm * 16 + (lane >> 2);
#pragma unroll
    for (int t = 0; t < 4; t++) {
        int n0 = colBase + t * 8 + (lane & 3) * 2;
        float2 bb = *(const float2*)(smem + biasOff + n0 * 4);
        {
            float v0 = fmaxf(c[t][0] + bb.x, 0.f);
            float v1 = fmaxf(c[t][1] + bb.y, 0.f);
            uint32_t hi, lo;
            split2(v0, v1, hi, lo);
            uint32_t o = (uint32_t)r0 * AST + (uint32_t)n0 * 2;
            *(uint32_t*)(smem + hiOff + o) = hi;
            *(uint32_t*)(smem + loOff + o) = lo;
        }
        {
            float v0 = fmaxf(c[t][2] + bb.x, 0.f);
            float v1 = fmaxf(c[t][3] + bb.y, 0.f);
            uint32_t hi, lo;
            split2(v0, v1, hi, lo);
            uint32_t o = (uint32_t)(r0 + 8) * AST + (uint32_t)n0 * 2;
            *(uint32_t*)(smem + hiOff + o) = hi;
            *(uint32_t*)(smem + loOff + o) = lo;
        }
    }
}

// ---------------------------------------------------------------------------
// Gather: 32-row tile -> (xHi,xLo), compile-time NTHR for full unroll.
// ---------------------------------------------------------------------------
template <int MODE, int NTHR>
__device__ __forceinline__ void do_gather(char* smem,
                                          const float* __restrict__ in,
                                          const float* __restrict__ prev,
                                          int row0, int logn, int off,
                                          uint32_t xHi, uint32_t xLo,
                                          int tg) {
    if (MODE == 0) {
        const float2* src = (const float2*)(in + (size_t)row0 * FD);
#pragma unroll
        for (int i = tg; i < TILE_R * 16; i += NTHR) {
            int r = i >> 4, cp = i & 15;
            float2 v = src[i];
            uint32_t hi, lo;
            split2(v.x, v.y, hi, lo);
            uint32_t o = (uint32_t)r * AST + (uint32_t)cp * 4;
            *(uint32_t*)(smem + xHi + o) = hi;
            *(uint32_t*)(smem + xLo + o) = lo;
        }
    } else {
        const int n = 1 << logn;
#pragma unroll
        for (int i = tg; i < TILE_R * 48; i += NTHR) {
            int r = i / 48, cp = i - r * 48;
            int gr = row0 + r;
            int b = gr >> logn, ii = gr & (n - 1);
            float2 v;
            if (cp < 16)
                v = *(const float2*)(in + (((size_t)b * (NLEAF - 1) + off + ii) << 5) + cp * 2);
            else
                v = *(const float2*)(prev + (((size_t)(b << (logn + 1)) + 2 * ii) << 5) + (cp * 2 - 32));
            uint32_t hi, lo;
            split2(v.x, v.y, hi, lo);
            uint32_t o = (uint32_t)r * AST + (uint32_t)cp * 4;
            *(uint32_t*)(smem + xHi + o) = hi;
            *(uint32_t*)(smem + xLo + o) = lo;
        }
    }
}

// ---------------------------------------------------------------------------
// MODE: 0 = leaf (in -> bufA), 1 = join A->B, 2 = join B->A
// ---------------------------------------------------------------------------
template <int NK1, int MODE>
__global__ void __launch_bounds__(THREADS, 1)
level_kernel(const float* __restrict__ in,
             const float* __restrict__ W3, const float* __restrict__ b1,
             const float* __restrict__ b2, const float* __restrict__ b3,
             int logn, int off, int ntiles) {
    extern __shared__ char smem[];
    uint32_t sb = smem_u32(smem);
    const int tid = threadIdx.x;

    // --- stage W3 (transposed [N][K], hi/lo) + biases ---
    for (int i = tid; i < HD * OD; i += THREADS) {
        int k = i / OD, n = i - k * OD;
        float v = W3[i];
        __nv_bfloat16 h = __float2bfloat16(v);
        __nv_bfloat16 l = __float2bfloat16(v - __bfloat162float(h));
        uint32_t o = (uint32_t)n * W3ST + (uint32_t)k * 2;
        *(__nv_bfloat16*)(smem + W3T_HI + o) = h;
        *(__nv_bfloat16*)(smem + W3T_LO + o) = l;
    }
    if (tid < HD) {
        ((float*)(smem + B1OFF))[tid] = b1[tid];
        ((float*)(smem + B2OFF))[tid] = b2[tid];
    }
    if (tid < OD) ((float*)(smem + B3OFF))[tid] = b3[tid];
    __syncthreads();

    const uint4* frag1 = (MODE == 0) ? g_fragL1 : g_fragJ1;
    const uint4* frag2 = (MODE == 0) ? g_fragL2 : g_fragJ2;

    // --- group decomposition (R12) ---
    const int grp = tid >> 8;
    const int gtid = tid & 255;
    const int gwid = gtid >> 5;
    const int lane = tid & 31;
    const int wm = gwid & 1;
    const int wn = gwid >> 1;
    const int barid = grp + 1;

    const uint32_t gbase = (uint32_t)grp * GRP_STRIDE;
    const uint32_t xHi = gbase + X_HI_OFF, xLo = gbase + X_LO_OFF;
    const uint32_t hHi = gbase + H_HI_OFF, hLo = gbase + H_LO_OFF;

    const float* prev = (MODE == 1) ? g_bufA : g_bufB;
    float* dst = (MODE == 0) ? g_bufA : ((MODE == 1) ? g_bufB : g_bufA);
    const int step = 2 * gridDim.x;

    for (int t = 2 * blockIdx.x + grp; t < ntiles; t += step) {
        const int row0 = t * TILE_R;

        do_gather<MODE, GTHREADS>(smem, in, prev, row0, logn, off, xHi, xLo, gtid);
        BAR_GRP(barid);

        // ---- layer 1: X[32 x K1] @ W1 -> H ----
        {
            float c[4][4];
            gemm3_frag<2, NK1>(sb, xHi, xLo, frag1, wn * 32, lane, wm, c);
            epi128(smem, c, B1OFF, hHi, hLo, lane, wm, wn * 32);
        }
        BAR_GRP(barid);

        // ---- layer 2: H[32 x 128] @ W2 -> X (X dead) ----
        {
            float c[4][4];
            gemm3_frag<2, 8>(sb, hHi, hLo, frag2, wn * 32, lane, wm, c);
            epi128(smem, c, B2OFF, xHi, xLo, lane, wm, wn * 32);
        }
        BAR_GRP(barid);

        // ---- layer 3: X[32 x 128] @ W3T(smem) -> gmem fp32 [32 x 32] ----
        {
            float c[1][4];
            gemm3_x2<1, 8>(sb, xHi, xLo, AST, W3T_HI, W3T_LO, W3ST,
                           wn * 8, lane, wm, c);
            int r0 = row0 + wm * 16 + (lane >> 2);
            int n0 = wn * 8 + (lane & 3) * 2;
            float2 bb = *(const float2*)(smem + B3OFF + n0 * 4);
            float2 v0 = make_float2(c[0][0] + bb.x, c[0][1] + bb.y);
            float2 v1 = make_float2(c[0][2] + bb.x, c[0][3] + bb.y);
            *(float2*)(dst + (size_t)r0 * OD + n0) = v0;
            *(float2*)(dst + (size_t)(r0 + 8) * OD + n0) = v1;
        }
        BAR_GRP(barid);
    }
}

// ---------------------------------------------------------------------------
__global__ void extract_kernel(float* __restrict__ out) {
    int b = blockIdx.x * blockDim.x + threadIdx.x;
    if (b < NB) out[b] = g_bufA[(size_t)b * OD];
}

// ---------------------------------------------------------------------------
extern "C" void kernel_launch(void* const* d_in, const int* in_sizes, int n_in,
                              void* d_out, int out_size) {
    const float* leaf_feats = (const float*)d_in[0];
    const float* internal   = (const float*)d_in[1];
    const float* sW1 = (const float*)d_in[2];
    const float* sb1 = (const float*)d_in[3];
    const float* sW2 = (const float*)d_in[4];
    const float* sb2 = (const float*)d_in[5];
    const float* sW3 = (const float*)d_in[6];
    const float* sb3 = (const float*)d_in[7];
    const float* jW1 = (const float*)d_in[8];
    const float* jb1 = (const float*)d_in[9];
    const float* jW2 = (const float*)d_in[10];
    const float* jb2 = (const float*)d_in[11];
    const float* jW3 = (const float*)d_in[12];
    const float* jb3 = (const float*)d_in[13];
    float* out = (float*)d_out;

    cudaFuncSetAttribute(level_kernel<2, 0>, cudaFuncAttributeMaxDynamicSharedMemorySize, SMEM_TOTAL);
    cudaFuncSetAttribute(level_kernel<6, 1>, cudaFuncAttributeMaxDynamicSharedMemorySize, SMEM_TOTAL);
    cudaFuncSetAttribute(level_kernel<6, 2>, cudaFuncAttributeMaxDynamicSharedMemorySize, SMEM_TOTAL);

    // --- one-time frag prep (idempotent, graph-capturable) ---
    uint4* fL1; cudaGetSymbolAddress((void**)&fL1, g_fragL1);
    uint4* fL2; cudaGetSymbolAddress((void**)&fL2, g_fragL2);
    uint4* fJ1; cudaGetSymbolAddress((void**)&fJ1, g_fragJ1);
    uint4* fJ2; cudaGetSymbolAddress((void**)&fJ2, g_fragJ2);
    prep_frags<<<(8 * 2 * 32 + 255) / 256, 256>>>(sW1, fL1, 32);
    prep_frags<<<(8 * 8 * 32 + 255) / 256, 256>>>(sW2, fL2, 128);
    prep_frags<<<(8 * 6 * 32 + 255) / 256, 256>>>(jW1, fJ1, 96);
    prep_frags<<<(8 * 8 * 32 + 255) / 256, 256>>>(jW2, fJ2, 128);

    // Leaf level: K1 = 32, dst = bufA
    {
        int ntiles = (NB * NLEAF) / TILE_R;     // 65536
        int pairs = ntiles / 2;
        int grid = pairs < 148 ? pairs : 148;
        level_kernel<2, 0><<<grid, THREADS, SMEM_TOTAL>>>(
            leaf_feats, sW3, sb1, sb2, sb3, 0, 0, ntiles);
    }

    // Join levels n = 512..1; alternate A->B / B->A; final lands in bufA
    int off = 0;
    int mode = 1;
    for (int logn = 9; logn >= 0; --logn) {
        int n = 1 << logn;
        int ntiles = (NB * n) / TILE_R;
        int pairs = (ntiles + 1) / 2;
        int grid = pairs < 148 ? pairs : 148;
        if (mode == 1)
            level_kernel<6, 1><<<grid, THREADS, SMEM_TOTAL>>>(
                internal, jW3, jb1, jb2, jb3, logn, off, ntiles);
        else
            level_kernel<6, 2><<<grid, THREADS, SMEM_TOTAL>>>(
                internal, jW3, jb1, jb2, jb3, logn, off, ntiles);
        off += n;
        mode = (mode == 1) ? 2 : 1;
    }

    extract_kernel<<<(NB + 255) / 256, 256>>>(out);
}